// round 2
// baseline (speedup 1.0000x reference)
#include <cuda_runtime.h>
#include <math.h>

// Problem constants (fixed by the reference)
#define BB 4
#define SS 2048
#define HH 1024
#define NHEADS 16
#define DHEAD 64
#define MROWS (BB * SS)            // 8192
#define TENSOR_ELEMS (MROWS * HH)  // 8,388,608 per output tensor

// Scratch (allocation-free rule: __device__ globals)
__device__ float g_ln[MROWS * HH];  // layernorm output
__device__ float g_q[MROWS * HH];   // Q projection

// ---------------------------------------------------------------------------
// Packed fp32x2 helpers (Blackwell f32x2 pipe — 2 fp32 FMA per slot)
// ---------------------------------------------------------------------------
typedef unsigned long long u64t;

__device__ __forceinline__ void fma2(u64t& d, u64t a, u64t b) {
    asm("fma.rn.f32x2 %0, %1, %2, %0;" : "+l"(d) : "l"(a), "l"(b));
}
__device__ __forceinline__ u64t pack2(float x, float y) {
    u64t r; asm("mov.b64 %0, {%1, %2};" : "=l"(r) : "f"(x), "f"(y)); return r;
}
__device__ __forceinline__ float2 unpack2(u64t v) {
    float2 r; asm("mov.b64 {%0, %1}, %2;" : "=f"(r.x), "=f"(r.y) : "l"(v)); return r;
}
__device__ __forceinline__ void mul2(u64t& d, u64t a, u64t b) {
    asm("mul.rn.f32x2 %0, %1, %2;" : "=l"(d) : "l"(a), "l"(b));
}

// ---------------------------------------------------------------------------
// Kernel 1: LayerNorm. One block per row (8192 rows), 256 threads, float4.
// ---------------------------------------------------------------------------
__global__ __launch_bounds__(256)
void ln_kernel(const float* __restrict__ x,
               const float* __restrict__ w,
               const float* __restrict__ bvec,
               float* __restrict__ y)
{
    const int row = blockIdx.x;
    const int t = threadIdx.x;
    const float4 xv = ((const float4*)(x + (size_t)row * HH))[t];

    float s  = xv.x + xv.y + xv.z + xv.w;
    float ss = xv.x * xv.x + xv.y * xv.y + xv.z * xv.z + xv.w * xv.w;
    #pragma unroll
    for (int o = 16; o > 0; o >>= 1) {
        s  += __shfl_xor_sync(0xFFFFFFFFu, s,  o);
        ss += __shfl_xor_sync(0xFFFFFFFFu, ss, o);
    }
    __shared__ float rs[8], rss[8];
    __shared__ float smu, srstd;
    const int wid = t >> 5, lane = t & 31;
    if (lane == 0) { rs[wid] = s; rss[wid] = ss; }
    __syncthreads();
    if (t == 0) {
        float a = 0.f, b2 = 0.f;
        #pragma unroll
        for (int i = 0; i < 8; i++) { a += rs[i]; b2 += rss[i]; }
        const float mu = a * (1.0f / HH);
        float var = b2 * (1.0f / HH) - mu * mu;
        smu = mu;
        srstd = rsqrtf(var + 1e-12f);
    }
    __syncthreads();
    const float mu = smu, rstd = srstd;
    const float4 wv = ((const float4*)w)[t];
    const float4 bv = ((const float4*)bvec)[t];
    float4 o;
    o.x = (xv.x - mu) * rstd * wv.x + bv.x;
    o.y = (xv.y - mu) * rstd * wv.y + bv.y;
    o.z = (xv.z - mu) * rstd * wv.z + bv.z;
    o.w = (xv.w - mu) * rstd * wv.w + bv.w;
    ((float4*)(y + (size_t)row * HH))[t] = o;
}

// ---------------------------------------------------------------------------
// Kernel 2/4: SGEMM NT  C[M,N] = A[M,K] @ B[N,K]^T (+bias), f32x2 inner loop.
// BM=BN=128, BK=16, 256 threads, 8x8 per-thread tile (4 packed pairs along N).
// ---------------------------------------------------------------------------
template<bool SPLIT>
__global__ __launch_bounds__(256)
void sgemm_nt(const float* __restrict__ A, const float* __restrict__ Bw,
              const float* __restrict__ bias,
              float* __restrict__ C0, float* __restrict__ C1, float* __restrict__ C2,
              int M, int N, int K)
{
    constexpr int BM = 128, BN = 128, BK = 16, PAD = 4;
    __shared__ float As[BK][BM + PAD];
    __shared__ float Bs[BK][BN + PAD];

    const int bm = blockIdx.y * BM;
    const int bn = blockIdx.x * BN;
    const int tid = threadIdx.x;

    const int lr = tid >> 2;        // 0..63 (row within half-tile)
    const int lc = (tid & 3) * 4;   // k offset: 0,4,8,12
    const int tr = (tid >> 4) * 8;  // 0..120
    const int tc = (tid & 15) * 8;  // 0..120

    u64t accp[8][4];
    #pragma unroll
    for (int i = 0; i < 8; i++)
        #pragma unroll
        for (int j = 0; j < 4; j++) accp[i][j] = 0ULL;

    for (int k0 = 0; k0 < K; k0 += BK) {
        #pragma unroll
        for (int i = 0; i < 2; i++) {
            const int r = lr + i * 64;
            const float4 v = *(const float4*)(A  + (size_t)(bm + r) * K + k0 + lc);
            As[lc + 0][r] = v.x; As[lc + 1][r] = v.y;
            As[lc + 2][r] = v.z; As[lc + 3][r] = v.w;
            const float4 u = *(const float4*)(Bw + (size_t)(bn + r) * K + k0 + lc);
            Bs[lc + 0][r] = u.x; Bs[lc + 1][r] = u.y;
            Bs[lc + 2][r] = u.z; Bs[lc + 3][r] = u.w;
        }
        __syncthreads();
        #pragma unroll
        for (int kk = 0; kk < BK; kk++) {
            const float4 a0 = *(const float4*)&As[kk][tr];
            const float4 a1 = *(const float4*)&As[kk][tr + 4];
            const float4 b0 = *(const float4*)&Bs[kk][tc];
            const float4 b1 = *(const float4*)&Bs[kk][tc + 4];
            u64t rbp[4];
            rbp[0] = pack2(b0.x, b0.y); rbp[1] = pack2(b0.z, b0.w);
            rbp[2] = pack2(b1.x, b1.y); rbp[3] = pack2(b1.z, b1.w);
            u64t rap[8];
            rap[0] = pack2(a0.x, a0.x); rap[1] = pack2(a0.y, a0.y);
            rap[2] = pack2(a0.z, a0.z); rap[3] = pack2(a0.w, a0.w);
            rap[4] = pack2(a1.x, a1.x); rap[5] = pack2(a1.y, a1.y);
            rap[6] = pack2(a1.z, a1.z); rap[7] = pack2(a1.w, a1.w);
            #pragma unroll
            for (int i = 0; i < 8; i++)
                #pragma unroll
                for (int j = 0; j < 4; j++)
                    fma2(accp[i][j], rap[i], rbp[j]);
        }
        __syncthreads();
    }

    #pragma unroll
    for (int i = 0; i < 8; i++) {
        const int gm = bm + tr + i;
        #pragma unroll
        for (int j4 = 0; j4 < 4; j4++) {
            const float2 pr = unpack2(accp[i][j4]);
            #pragma unroll
            for (int h = 0; h < 2; h++) {
                const int gn = bn + tc + j4 * 2 + h;
                float v = (h == 0) ? pr.x : pr.y;
                if (bias) v += bias[gn];
                if (SPLIT) {
                    const int sec = gn >> 10;
                    const int col = gn & 1023;
                    float* Cp = (sec == 0) ? C0 : ((sec == 1) ? C1 : C2);
                    Cp[(size_t)gm * 1024 + col] = v;
                } else {
                    C0[(size_t)gm * N + gn] = v;
                }
            }
        }
    }
}

// ---------------------------------------------------------------------------
// Kernel 3: fp32 flash attention with f32x2 inner loops.
// grid (S/128, NHEADS, BB); 128 threads; each thread owns one q row.
// ---------------------------------------------------------------------------
__global__ __launch_bounds__(128)
void attn_kernel(const float* __restrict__ Q, const float* __restrict__ Kk,
                 const float* __restrict__ Vv, const float* __restrict__ mask,
                 float* __restrict__ Ctx)
{
    const int b = blockIdx.z, h = blockIdx.y, qt = blockIdx.x;
    const int t = threadIdx.x;
    const int qrow = qt * 128 + t;

    u64t qp[32];  // packed q pairs
    {
        const float4* qsrc = (const float4*)(Q + ((size_t)(b * SS + qrow) * HH + h * DHEAD));
        #pragma unroll
        for (int i = 0; i < 16; i++) {
            const float4 v = qsrc[i];
            qp[2 * i + 0] = pack2(v.x, v.y);
            qp[2 * i + 1] = pack2(v.z, v.w);
        }
    }

    u64t accp[32];
    #pragma unroll
    for (int d = 0; d < 32; d++) accp[d] = 0ULL;
    float mrow = -INFINITY, lrow = 0.f;

    __shared__ float Ks[32][DHEAD];
    __shared__ float Vs[32][DHEAD];
    __shared__ float Ms[32];
    const float scale = 0.125f;  // 1/sqrt(64)

    for (int kt = 0; kt < SS; kt += 32) {
        #pragma unroll
        for (int i = 0; i < 4; i++) {
            const int f = t + i * 128;
            const int r = f >> 4, c = f & 15;
            const size_t base = (size_t)(b * SS + kt + r) * HH + h * DHEAD + c * 4;
            *(float4*)&Ks[r][c * 4] = *(const float4*)(Kk + base);
            *(float4*)&Vs[r][c * 4] = *(const float4*)(Vv + base);
        }
        if (t < 32) Ms[t] = mask[b * SS + kt + t];
        __syncthreads();

        float sc[32];
        #pragma unroll
        for (int j = 0; j < 32; j++) {
            u64t s0 = 0ULL, s1 = 0ULL;
            const float4* k4 = (const float4*)Ks[j];
            #pragma unroll
            for (int d4 = 0; d4 < 8; d4++) {
                const float4 ka = k4[2 * d4];
                const float4 kb = k4[2 * d4 + 1];
                fma2(s0, qp[4 * d4 + 0], pack2(ka.x, ka.y));
                fma2(s1, qp[4 * d4 + 1], pack2(ka.z, ka.w));
                fma2(s0, qp[4 * d4 + 2], pack2(kb.x, kb.y));
                fma2(s1, qp[4 * d4 + 3], pack2(kb.z, kb.w));
            }
            const float2 e0 = unpack2(s0);
            const float2 e1 = unpack2(s1);
            sc[j] = (e0.x + e0.y + e1.x + e1.y) * scale + Ms[j];
        }

        float tmax = mrow;
        #pragma unroll
        for (int j = 0; j < 32; j++) tmax = fmaxf(tmax, sc[j]);
        const float corr = __expf(mrow - tmax);
        lrow *= corr;
        const u64t corrp = pack2(corr, corr);
        #pragma unroll
        for (int d = 0; d < 32; d++) {
            u64t tmp; mul2(tmp, accp[d], corrp); accp[d] = tmp;
        }

        #pragma unroll
        for (int j = 0; j < 32; j++) {
            const float p = __expf(sc[j] - tmax);
            lrow += p;
            const u64t pp = pack2(p, p);
            const float4* v4 = (const float4*)Vs[j];
            #pragma unroll
            for (int d4 = 0; d4 < 16; d4++) {
                const float4 vv = v4[d4];
                fma2(accp[2 * d4 + 0], pp, pack2(vv.x, vv.y));
                fma2(accp[2 * d4 + 1], pp, pack2(vv.z, vv.w));
            }
        }
        mrow = tmax;
        __syncthreads();
    }

    const float inv = 1.0f / lrow;
    float4* op = (float4*)(Ctx + ((size_t)(b * SS + qrow) * HH + h * DHEAD));
    #pragma unroll
    for (int i = 0; i < 16; i++) {
        const float2 p0 = unpack2(accp[2 * i + 0]);
        const float2 p1 = unpack2(accp[2 * i + 1]);
        float4 o;
        o.x = p0.x * inv; o.y = p0.y * inv;
        o.z = p1.x * inv; o.w = p1.y * inv;
        op[i] = o;
    }
}

// ---------------------------------------------------------------------------
// Launch
// ---------------------------------------------------------------------------
extern "C" void kernel_launch(void* const* d_in, const int* in_sizes, int n_in,
                              void* d_out, int out_size)
{
    const float* input = (const float*)d_in[0];
    const float* mask  = (const float*)d_in[1];
    const float* nw    = (const float*)d_in[2];
    const float* nb    = (const float*)d_in[3];
    const float* qkvw  = (const float*)d_in[4];
    const float* qkvb  = (const float*)d_in[5];
    const float* ow    = (const float*)d_in[6];

    float* out     = (float*)d_out;                 // [B,S,H] output
    float* key_out = out + (size_t)TENSOR_ELEMS;    // [B,S,H] key_layer
    float* val_out = out + (size_t)2 * TENSOR_ELEMS;// [B,S,H] value_layer
    float* ctx_out = out + (size_t)3 * TENSOR_ELEMS;// [B,S,H] context_layer

    float *ln_ptr = nullptr, *q_ptr = nullptr;
    cudaGetSymbolAddress((void**)&ln_ptr, g_ln);
    cudaGetSymbolAddress((void**)&q_ptr,  g_q);

    // 1) LayerNorm
    ln_kernel<<<MROWS, 256>>>(input, nw, nb, ln_ptr);

    // 2) QKV GEMM: [8192,1024] x [3072,1024]^T, split into q scratch / key / value
    {
        dim3 grid(3072 / 128, MROWS / 128);
        sgemm_nt<true><<<grid, 256>>>(ln_ptr, qkvw, qkvb,
                                      q_ptr, key_out, val_out,
                                      MROWS, 3 * HH, HH);
    }

    // 3) Flash attention -> context_layer
    {
        dim3 grid(SS / 128, NHEADS, BB);
        attn_kernel<<<grid, 128>>>(q_ptr, key_out, val_out, mask, ctx_out);
    }

    // 4) Output projection: [8192,1024] x [1024,1024]^T -> output
    {
        dim3 grid(1024 / 128, MROWS / 128);
        sgemm_nt<false><<<grid, 256>>>(ctx_out, ow, nullptr,
                                       out, nullptr, nullptr,
                                       MROWS, HH, HH);
    }
}

// round 6
// speedup vs baseline: 1.3222x; 1.3222x over previous
#include <cuda_runtime.h>
#include <cuda_bf16.h>
#include <math.h>
#include <stdint.h>

// Problem constants (fixed by the reference)
#define BB 4
#define SS 2048
#define HH 1024
#define NHEADS 16
#define DHEAD 64
#define MROWS (BB * SS)            // 8192
#define TENSOR_ELEMS (MROWS * HH)  // 8,388,608 per output tensor

// ---------------------------------------------------------------------------
// Scratch (__device__ globals; no runtime allocation allowed)
// ---------------------------------------------------------------------------
__device__ __nv_bfloat16 g_a_hi[MROWS * HH];      // LN output hi
__device__ __nv_bfloat16 g_a_lo[MROWS * HH];      // LN output lo
__device__ __nv_bfloat16 g_w_hi[3 * HH * HH];     // qkv weight hi
__device__ __nv_bfloat16 g_w_lo[3 * HH * HH];     // qkv weight lo
__device__ __nv_bfloat16 g_ow_hi[HH * HH];        // out-proj weight hi
__device__ __nv_bfloat16 g_ow_lo[HH * HH];        // out-proj weight lo
__device__ __nv_bfloat16 g_c_hi[MROWS * HH];      // context hi
__device__ __nv_bfloat16 g_c_lo[MROWS * HH];      // context lo
__device__ float g_q[MROWS * HH];                  // Q projection (fp32)

// ---------------------------------------------------------------------------
// PTX helpers — target-portable (sm_80+): cp.async, ldmatrix, mma.sync
// ---------------------------------------------------------------------------
__device__ __forceinline__ uint32_t smem_u32(const void* p) {
    uint32_t a;
    asm("{ .reg .u64 t; cvta.to.shared.u64 t, %1; cvt.u32.u64 %0, t; }" : "=r"(a) : "l"(p));
    return a;
}
#define CP_ASYNC16(dst, src) \
    asm volatile("cp.async.cg.shared.global [%0], [%1], 16;" :: "r"(dst), "l"(src))
#define CP_COMMIT() asm volatile("cp.async.commit_group;" ::: "memory")
#define CP_WAIT0()  asm volatile("cp.async.wait_group 0;" ::: "memory")

// ---------------------------------------------------------------------------
// Kernel 1: LayerNorm -> bf16 hi/lo split. One block per row, 256 threads.
// ---------------------------------------------------------------------------
__global__ __launch_bounds__(256)
void ln_kernel(const float* __restrict__ x,
               const float* __restrict__ w,
               const float* __restrict__ bvec,
               __nv_bfloat16* __restrict__ yhi,
               __nv_bfloat16* __restrict__ ylo)
{
    const int row = blockIdx.x;
    const int t = threadIdx.x;
    const float4 xv = ((const float4*)(x + (size_t)row * HH))[t];

    float s  = xv.x + xv.y + xv.z + xv.w;
    float ss = xv.x * xv.x + xv.y * xv.y + xv.z * xv.z + xv.w * xv.w;
    #pragma unroll
    for (int o = 16; o > 0; o >>= 1) {
        s  += __shfl_xor_sync(0xFFFFFFFFu, s,  o);
        ss += __shfl_xor_sync(0xFFFFFFFFu, ss, o);
    }
    __shared__ float rs[8], rss[8];
    __shared__ float smu, srstd;
    const int wid = t >> 5, lane = t & 31;
    if (lane == 0) { rs[wid] = s; rss[wid] = ss; }
    __syncthreads();
    if (t == 0) {
        float a = 0.f, b2 = 0.f;
        #pragma unroll
        for (int i = 0; i < 8; i++) { a += rs[i]; b2 += rss[i]; }
        const float mu = a * (1.0f / HH);
        float var = b2 * (1.0f / HH) - mu * mu;
        smu = mu;
        srstd = rsqrtf(var + 1e-12f);
    }
    __syncthreads();
    const float mu = smu, rstd = srstd;
    const float4 wv = ((const float4*)w)[t];
    const float4 bv = ((const float4*)bvec)[t];
    float v[4];
    v[0] = (xv.x - mu) * rstd * wv.x + bv.x;
    v[1] = (xv.y - mu) * rstd * wv.y + bv.y;
    v[2] = (xv.z - mu) * rstd * wv.z + bv.z;
    v[3] = (xv.w - mu) * rstd * wv.w + bv.w;
    __nv_bfloat16 hi[4], lo[4];
    #pragma unroll
    for (int i = 0; i < 4; i++) {
        hi[i] = __float2bfloat16_rn(v[i]);
        lo[i] = __float2bfloat16_rn(v[i] - __bfloat162float(hi[i]));
    }
    const size_t base = (size_t)row * HH + t * 4;
    *(uint64_t*)(yhi + base) = *(uint64_t*)hi;
    *(uint64_t*)(ylo + base) = *(uint64_t*)lo;
}

// ---------------------------------------------------------------------------
// Kernel: fp32 -> bf16 hi/lo split (weights, context)
// ---------------------------------------------------------------------------
__global__ __launch_bounds__(256)
void split_kernel(const float* __restrict__ x,
                  __nv_bfloat16* __restrict__ hi,
                  __nv_bfloat16* __restrict__ lo, int n4)
{
    const int i = blockIdx.x * 256 + threadIdx.x;
    if (i >= n4) return;
    const float4 v = ((const float4*)x)[i];
    __nv_bfloat16 h[4], l[4];
    const float vv[4] = {v.x, v.y, v.z, v.w};
    #pragma unroll
    for (int j = 0; j < 4; j++) {
        h[j] = __float2bfloat16_rn(vv[j]);
        l[j] = __float2bfloat16_rn(vv[j] - __bfloat162float(h[j]));
    }
    ((uint64_t*)hi)[i] = *(uint64_t*)h;
    ((uint64_t*)lo)[i] = *(uint64_t*)l;
}

// ---------------------------------------------------------------------------
// bf16 3-pass split GEMM on tensor cores via mma.sync (HMMA).
// C[M,N] = Ah@Bh^T + Ah@Bl^T + Al@Bh^T (+bias).
// Tile 128x128, BK=32, 256 threads (8 warps, 2x4), warp tile 64x32.
// cp.async double-buffered; ldmatrix from padded smem (stride 40 bf16).
// ---------------------------------------------------------------------------
template<bool SPLIT>
__global__ __launch_bounds__(256)
void gemm_mma(const __nv_bfloat16* __restrict__ Ahi, const __nv_bfloat16* __restrict__ Alo,
              const __nv_bfloat16* __restrict__ Bhi, const __nv_bfloat16* __restrict__ Blo,
              const float* __restrict__ bias,
              float* __restrict__ C0, float* __restrict__ C1, float* __restrict__ C2,
              int K, int N)
{
    constexpr int BM = 128, BN = 128, BK = 32, STR = 40;  // STR in bf16 elems
    __shared__ __nv_bfloat16 As[2][BM * STR];
    __shared__ __nv_bfloat16 Bs[2][BN * STR];

    const int t = threadIdx.x;
    const int wid = t >> 5, lane = t & 31;
    const int warp_m = wid >> 2;   // 0..1  -> 64-row slab
    const int warp_n = wid & 3;    // 0..3  -> 32-col slab
    const int bm = blockIdx.y * BM;
    const int bn = blockIdx.x * BN;

    float acc[4][4][4];
    #pragma unroll
    for (int i = 0; i < 4; i++)
        #pragma unroll
        for (int j = 0; j < 4; j++)
            #pragma unroll
            for (int r = 0; r < 4; r++) acc[i][j][r] = 0.f;

    const uint32_t sA[2] = { smem_u32(As[0]), smem_u32(As[1]) };
    const uint32_t sB[2] = { smem_u32(Bs[0]), smem_u32(Bs[1]) };

    const int nkp = K / BK;        // k-tiles per pass
    const int nk = 3 * nkp;        // 3 split passes

    // per-thread load slots: id in [0,512): row=id/4, 16B chunk=id%4
    const int r0 = t >> 2, ch = (t & 3) * 8;
    const uint32_t soff0 = (uint32_t)(r0 * STR + ch) * 2;
    const uint32_t soff1 = (uint32_t)((r0 + 64) * STR + ch) * 2;

    // stage issue
    auto issue = [&](int i) {
        const int s = i & 1;
        const int p = i / nkp;
        const int k0 = (i - p * nkp) * BK;
        const __nv_bfloat16* Ap = (p == 2) ? Alo : Ahi;
        const __nv_bfloat16* Bp = (p == 1) ? Blo : Bhi;
        CP_ASYNC16(sA[s] + soff0, Ap + (size_t)(bm + r0) * K + k0 + ch);
        CP_ASYNC16(sA[s] + soff1, Ap + (size_t)(bm + r0 + 64) * K + k0 + ch);
        CP_ASYNC16(sB[s] + soff0, Bp + (size_t)(bn + r0) * K + k0 + ch);
        CP_ASYNC16(sB[s] + soff1, Bp + (size_t)(bn + r0 + 64) * K + k0 + ch);
        CP_COMMIT();
    };

    issue(0);
    for (int i = 0; i < nk; i++) {
        CP_WAIT0();
        __syncthreads();
        if (i + 1 < nk) issue(i + 1);
        const int s = i & 1;

        #pragma unroll
        for (int ks = 0; ks < 2; ks++) {
            uint32_t a[4][4];
            uint32_t b[4][2];
            #pragma unroll
            for (int mt = 0; mt < 4; mt++) {
                const int row = warp_m * 64 + mt * 16 + (lane & 15);
                const int kc = ks * 16 + ((lane >> 4) * 8);
                const uint32_t ad = sA[s] + (uint32_t)(row * STR + kc) * 2;
                asm volatile("ldmatrix.sync.aligned.m8n8.x4.shared.b16 {%0,%1,%2,%3}, [%4];"
                             : "=r"(a[mt][0]), "=r"(a[mt][1]), "=r"(a[mt][2]), "=r"(a[mt][3])
                             : "r"(ad));
            }
            #pragma unroll
            for (int nt = 0; nt < 4; nt++) {
                const int row = warp_n * 32 + nt * 8 + (lane & 7);
                const int kc = ks * 16 + (((lane >> 3) & 1) * 8);
                const uint32_t bd = sB[s] + (uint32_t)(row * STR + kc) * 2;
                asm volatile("ldmatrix.sync.aligned.m8n8.x2.shared.b16 {%0,%1}, [%2];"
                             : "=r"(b[nt][0]), "=r"(b[nt][1])
                             : "r"(bd));
            }
            #pragma unroll
            for (int mt = 0; mt < 4; mt++)
                #pragma unroll
                for (int nt = 0; nt < 4; nt++) {
                    asm volatile(
                        "mma.sync.aligned.m16n8k16.row.col.f32.bf16.bf16.f32 "
                        "{%0,%1,%2,%3}, {%4,%5,%6,%7}, {%8,%9}, {%0,%1,%2,%3};"
                        : "+f"(acc[mt][nt][0]), "+f"(acc[mt][nt][1]),
                          "+f"(acc[mt][nt][2]), "+f"(acc[mt][nt][3])
                        : "r"(a[mt][0]), "r"(a[mt][1]), "r"(a[mt][2]), "r"(a[mt][3]),
                          "r"(b[nt][0]), "r"(b[nt][1]));
                }
        }
    }

    // Epilogue: c frag -> (m = base + lane/4 [+8], n = base + (lane%4)*2 [+1])
    const int sec = bn >> 10;  // tile never straddles a 1024-col section
    float* Csec = SPLIT ? ((sec == 0) ? C0 : ((sec == 1) ? C1 : C2)) : C0;
    const int cstride = SPLIT ? 1024 : N;

    #pragma unroll
    for (int mt = 0; mt < 4; mt++) {
        const int m0 = bm + warp_m * 64 + mt * 16 + (lane >> 2);
        #pragma unroll
        for (int nt = 0; nt < 4; nt++) {
            const int n0 = bn + warp_n * 32 + nt * 8 + (lane & 3) * 2;
            float b0 = 0.f, b1 = 0.f;
            if (bias) { b0 = bias[n0]; b1 = bias[n0 + 1]; }
            const int col = SPLIT ? (n0 & 1023) : n0;
            float2 v0 = { acc[mt][nt][0] + b0, acc[mt][nt][1] + b1 };
            float2 v1 = { acc[mt][nt][2] + b0, acc[mt][nt][3] + b1 };
            *(float2*)(Csec + (size_t)m0 * cstride + col)       = v0;
            *(float2*)(Csec + (size_t)(m0 + 8) * cstride + col) = v1;
        }
    }
}

// ---------------------------------------------------------------------------
// Kernel 3: fp32 flash attention (round-0 scalar version, best measured).
// ---------------------------------------------------------------------------
__global__ __launch_bounds__(128)
void attn_kernel(const float* __restrict__ Q, const float* __restrict__ Kk,
                 const float* __restrict__ Vv, const float* __restrict__ mask,
                 float* __restrict__ Ctx)
{
    const int b = blockIdx.z, h = blockIdx.y, qt = blockIdx.x;
    const int t = threadIdx.x;
    const int qrow = qt * 128 + t;

    float q[DHEAD];
    {
        const float4* qp = (const float4*)(Q + ((size_t)(b * SS + qrow) * HH + h * DHEAD));
        #pragma unroll
        for (int i = 0; i < 16; i++) {
            const float4 v = qp[i];
            q[4 * i + 0] = v.x; q[4 * i + 1] = v.y;
            q[4 * i + 2] = v.z; q[4 * i + 3] = v.w;
        }
    }

    float acc[DHEAD];
    #pragma unroll
    for (int d = 0; d < DHEAD; d++) acc[d] = 0.f;
    float mrow = -INFINITY, lrow = 0.f;

    __shared__ float Ks[32][DHEAD];
    __shared__ float Vs[32][DHEAD];
    __shared__ float Ms[32];
    const float scale = 0.125f;

    for (int kt = 0; kt < SS; kt += 32) {
        #pragma unroll
        for (int i = 0; i < 4; i++) {
            const int f = t + i * 128;
            const int r = f >> 4, c = f & 15;
            const size_t base = (size_t)(b * SS + kt + r) * HH + h * DHEAD + c * 4;
            *(float4*)&Ks[r][c * 4] = *(const float4*)(Kk + base);
            *(float4*)&Vs[r][c * 4] = *(const float4*)(Vv + base);
        }
        if (t < 32) Ms[t] = mask[b * SS + kt + t];
        __syncthreads();

        float sc[32];
        #pragma unroll
        for (int j = 0; j < 32; j++) {
            float s = 0.f;
            const float4* k4 = (const float4*)Ks[j];
            #pragma unroll
            for (int d4 = 0; d4 < 16; d4++) {
                const float4 kv = k4[d4];
                s = fmaf(q[4 * d4 + 0], kv.x, s);
                s = fmaf(q[4 * d4 + 1], kv.y, s);
                s = fmaf(q[4 * d4 + 2], kv.z, s);
                s = fmaf(q[4 * d4 + 3], kv.w, s);
            }
            sc[j] = s * scale + Ms[j];
        }

        float tmax = mrow;
        #pragma unroll
        for (int j = 0; j < 32; j++) tmax = fmaxf(tmax, sc[j]);
        const float corr = __expf(mrow - tmax);
        lrow *= corr;
        #pragma unroll
        for (int d = 0; d < DHEAD; d++) acc[d] *= corr;

        #pragma unroll
        for (int j = 0; j < 32; j++) {
            const float p = __expf(sc[j] - tmax);
            lrow += p;
            const float4* v4 = (const float4*)Vs[j];
            #pragma unroll
            for (int d4 = 0; d4 < 16; d4++) {
                const float4 vv = v4[d4];
                acc[4 * d4 + 0] = fmaf(p, vv.x, acc[4 * d4 + 0]);
                acc[4 * d4 + 1] = fmaf(p, vv.y, acc[4 * d4 + 1]);
                acc[4 * d4 + 2] = fmaf(p, vv.z, acc[4 * d4 + 2]);
                acc[4 * d4 + 3] = fmaf(p, vv.w, acc[4 * d4 + 3]);
            }
        }
        mrow = tmax;
        __syncthreads();
    }

    const float inv = 1.0f / lrow;
    float4* op = (float4*)(Ctx + ((size_t)(b * SS + qrow) * HH + h * DHEAD));
    #pragma unroll
    for (int i = 0; i < 16; i++) {
        float4 o;
        o.x = acc[4 * i + 0] * inv;
        o.y = acc[4 * i + 1] * inv;
        o.z = acc[4 * i + 2] * inv;
        o.w = acc[4 * i + 3] * inv;
        op[i] = o;
    }
}

// ---------------------------------------------------------------------------
// Launch
// ---------------------------------------------------------------------------
extern "C" void kernel_launch(void* const* d_in, const int* in_sizes, int n_in,
                              void* d_out, int out_size)
{
    const float* input = (const float*)d_in[0];
    const float* mask  = (const float*)d_in[1];
    const float* nw    = (const float*)d_in[2];
    const float* nb    = (const float*)d_in[3];
    const float* qkvw  = (const float*)d_in[4];
    const float* qkvb  = (const float*)d_in[5];
    const float* ow    = (const float*)d_in[6];

    float* out     = (float*)d_out;
    float* key_out = out + (size_t)TENSOR_ELEMS;
    float* val_out = out + (size_t)2 * TENSOR_ELEMS;
    float* ctx_out = out + (size_t)3 * TENSOR_ELEMS;

    __nv_bfloat16 *a_hi, *a_lo, *w_hi, *w_lo, *ow_hi, *ow_lo, *c_hi, *c_lo;
    float* q_ptr;
    cudaGetSymbolAddress((void**)&a_hi, g_a_hi);
    cudaGetSymbolAddress((void**)&a_lo, g_a_lo);
    cudaGetSymbolAddress((void**)&w_hi, g_w_hi);
    cudaGetSymbolAddress((void**)&w_lo, g_w_lo);
    cudaGetSymbolAddress((void**)&ow_hi, g_ow_hi);
    cudaGetSymbolAddress((void**)&ow_lo, g_ow_lo);
    cudaGetSymbolAddress((void**)&c_hi, g_c_hi);
    cudaGetSymbolAddress((void**)&c_lo, g_c_lo);
    cudaGetSymbolAddress((void**)&q_ptr, g_q);

    // 1) LayerNorm -> bf16 split
    ln_kernel<<<MROWS, 256>>>(input, nw, nb, a_hi, a_lo);

    // 2) Weight splits
    split_kernel<<<(3 * HH * HH / 4 + 255) / 256, 256>>>(qkvw, w_hi, w_lo, 3 * HH * HH / 4);
    split_kernel<<<(HH * HH / 4 + 255) / 256, 256>>>(ow, ow_hi, ow_lo, HH * HH / 4);

    // 3) QKV GEMM (tensor cores via mma.sync): [8192,1024] x [3072,1024]^T
    {
        dim3 grid(3072 / 128, MROWS / 128);
        gemm_mma<true><<<grid, 256>>>(a_hi, a_lo, w_hi, w_lo, qkvb,
                                      q_ptr, key_out, val_out, HH, 3 * HH);
    }

    // 4) Flash attention -> context_layer
    {
        dim3 grid(SS / 128, NHEADS, BB);
        attn_kernel<<<grid, 128>>>(q_ptr, key_out, val_out, mask, ctx_out);
    }

    // 5) Context split + output projection (tensor cores)
    split_kernel<<<(TENSOR_ELEMS / 4 + 255) / 256, 256>>>(ctx_out, c_hi, c_lo, TENSOR_ELEMS / 4);
    {
        dim3 grid(HH / 128, MROWS / 128);
        gemm_mma<false><<<grid, 256>>>(c_hi, c_lo, ow_hi, ow_lo, nullptr,
                                       out, nullptr, nullptr, HH, HH);
    }
}

// round 8
// speedup vs baseline: 2.7819x; 2.1040x over previous
#include <cuda_runtime.h>
#include <cuda_bf16.h>
#include <math.h>
#include <stdint.h>

// Problem constants (fixed by the reference)
#define BB 4
#define SS 2048
#define HH 1024
#define NHEADS 16
#define DHEAD 64
#define MROWS (BB * SS)            // 8192
#define TENSOR_ELEMS (MROWS * HH)  // 8,388,608 per output tensor

// ---------------------------------------------------------------------------
// Scratch (__device__ globals; no runtime allocation allowed)
// ---------------------------------------------------------------------------
__device__ __nv_bfloat16 g_a_hi[MROWS * HH];
__device__ __nv_bfloat16 g_a_lo[MROWS * HH];
__device__ __nv_bfloat16 g_w_hi[3 * HH * HH];
__device__ __nv_bfloat16 g_w_lo[3 * HH * HH];
__device__ __nv_bfloat16 g_ow_hi[HH * HH];
__device__ __nv_bfloat16 g_ow_lo[HH * HH];
__device__ __nv_bfloat16 g_q_hi[MROWS * HH];
__device__ __nv_bfloat16 g_q_lo[MROWS * HH];
__device__ __nv_bfloat16 g_k_hi[MROWS * HH];
__device__ __nv_bfloat16 g_k_lo[MROWS * HH];
__device__ __nv_bfloat16 g_v_hi[MROWS * HH];
__device__ __nv_bfloat16 g_v_lo[MROWS * HH];
__device__ __nv_bfloat16 g_c_hi[MROWS * HH];
__device__ __nv_bfloat16 g_c_lo[MROWS * HH];

// ---------------------------------------------------------------------------
// PTX helpers — target-portable (sm_80+)
// ---------------------------------------------------------------------------
__device__ __forceinline__ uint32_t smem_u32(const void* p) {
    uint32_t a;
    asm("{ .reg .u64 t; cvta.to.shared.u64 t, %1; cvt.u32.u64 %0, t; }" : "=r"(a) : "l"(p));
    return a;
}
#define CP_ASYNC16(dst, src) \
    asm volatile("cp.async.cg.shared.global [%0], [%1], 16;" :: "r"(dst), "l"(src))
#define CP_COMMIT() asm volatile("cp.async.commit_group;" ::: "memory")
#define CP_WAIT0()  asm volatile("cp.async.wait_group 0;" ::: "memory")

__device__ __forceinline__ void ldm_x4(uint32_t* r, uint32_t addr) {
    asm volatile("ldmatrix.sync.aligned.m8n8.x4.shared.b16 {%0,%1,%2,%3}, [%4];"
                 : "=r"(r[0]), "=r"(r[1]), "=r"(r[2]), "=r"(r[3]) : "r"(addr));
}
__device__ __forceinline__ void ldm_x2(uint32_t* r, uint32_t addr) {
    asm volatile("ldmatrix.sync.aligned.m8n8.x2.shared.b16 {%0,%1}, [%2];"
                 : "=r"(r[0]), "=r"(r[1]) : "r"(addr));
}
__device__ __forceinline__ void ldm_x2t(uint32_t* r, uint32_t addr) {
    asm volatile("ldmatrix.sync.aligned.m8n8.x2.trans.shared.b16 {%0,%1}, [%2];"
                 : "=r"(r[0]), "=r"(r[1]) : "r"(addr));
}
__device__ __forceinline__ void mma16816(float* c, const uint32_t* a, const uint32_t* b) {
    asm volatile(
        "mma.sync.aligned.m16n8k16.row.col.f32.bf16.bf16.f32 "
        "{%0,%1,%2,%3}, {%4,%5,%6,%7}, {%8,%9}, {%0,%1,%2,%3};"
        : "+f"(c[0]), "+f"(c[1]), "+f"(c[2]), "+f"(c[3])
        : "r"(a[0]), "r"(a[1]), "r"(a[2]), "r"(a[3]), "r"(b[0]), "r"(b[1]));
}

// ---------------------------------------------------------------------------
// Kernel 1: LayerNorm -> bf16 hi/lo split. One block per row, 256 threads.
// ---------------------------------------------------------------------------
__global__ __launch_bounds__(256)
void ln_kernel(const float* __restrict__ x,
               const float* __restrict__ w,
               const float* __restrict__ bvec,
               __nv_bfloat16* __restrict__ yhi,
               __nv_bfloat16* __restrict__ ylo)
{
    const int row = blockIdx.x;
    const int t = threadIdx.x;
    const float4 xv = ((const float4*)(x + (size_t)row * HH))[t];

    float s  = xv.x + xv.y + xv.z + xv.w;
    float ss = xv.x * xv.x + xv.y * xv.y + xv.z * xv.z + xv.w * xv.w;
    #pragma unroll
    for (int o = 16; o > 0; o >>= 1) {
        s  += __shfl_xor_sync(0xFFFFFFFFu, s,  o);
        ss += __shfl_xor_sync(0xFFFFFFFFu, ss, o);
    }
    __shared__ float rs[8], rss[8];
    __shared__ float smu, srstd;
    const int wid = t >> 5, lane = t & 31;
    if (lane == 0) { rs[wid] = s; rss[wid] = ss; }
    __syncthreads();
    if (t == 0) {
        float a = 0.f, b2 = 0.f;
        #pragma unroll
        for (int i = 0; i < 8; i++) { a += rs[i]; b2 += rss[i]; }
        const float mu = a * (1.0f / HH);
        float var = b2 * (1.0f / HH) - mu * mu;
        smu = mu;
        srstd = rsqrtf(var + 1e-12f);
    }
    __syncthreads();
    const float mu = smu, rstd = srstd;
    const float4 wv = ((const float4*)w)[t];
    const float4 bv = ((const float4*)bvec)[t];
    float v[4];
    v[0] = (xv.x - mu) * rstd * wv.x + bv.x;
    v[1] = (xv.y - mu) * rstd * wv.y + bv.y;
    v[2] = (xv.z - mu) * rstd * wv.z + bv.z;
    v[3] = (xv.w - mu) * rstd * wv.w + bv.w;
    __nv_bfloat16 hi[4], lo[4];
    #pragma unroll
    for (int i = 0; i < 4; i++) {
        hi[i] = __float2bfloat16_rn(v[i]);
        lo[i] = __float2bfloat16_rn(v[i] - __bfloat162float(hi[i]));
    }
    const size_t base = (size_t)row * HH + t * 4;
    *(uint64_t*)(yhi + base) = *(uint64_t*)hi;
    *(uint64_t*)(ylo + base) = *(uint64_t*)lo;
}

// ---------------------------------------------------------------------------
// Kernel: fp32 -> bf16 hi/lo split (weights)
// ---------------------------------------------------------------------------
__global__ __launch_bounds__(256)
void split_kernel(const float* __restrict__ x,
                  __nv_bfloat16* __restrict__ hi,
                  __nv_bfloat16* __restrict__ lo, int n4)
{
    const int i = blockIdx.x * 256 + threadIdx.x;
    if (i >= n4) return;
    const float4 v = ((const float4*)x)[i];
    __nv_bfloat16 h[4], l[4];
    const float vv[4] = {v.x, v.y, v.z, v.w};
    #pragma unroll
    for (int j = 0; j < 4; j++) {
        h[j] = __float2bfloat16_rn(vv[j]);
        l[j] = __float2bfloat16_rn(vv[j] - __bfloat162float(h[j]));
    }
    ((uint64_t*)hi)[i] = *(uint64_t*)h;
    ((uint64_t*)lo)[i] = *(uint64_t*)l;
}

// ---------------------------------------------------------------------------
// bf16 3-pass split GEMM (HMMA). SPLIT: per-section fp32 + bf16 hi/lo outputs.
// ---------------------------------------------------------------------------
template<bool SPLIT>
__global__ __launch_bounds__(256)
void gemm_mma(const __nv_bfloat16* __restrict__ Ahi, const __nv_bfloat16* __restrict__ Alo,
              const __nv_bfloat16* __restrict__ Bhi, const __nv_bfloat16* __restrict__ Blo,
              const float* __restrict__ bias,
              float* __restrict__ F1, float* __restrict__ F2,      // key/value fp32
              float* __restrict__ C0,                              // plain output (non-split)
              __nv_bfloat16* __restrict__ H0, __nv_bfloat16* __restrict__ L0,
              __nv_bfloat16* __restrict__ H1, __nv_bfloat16* __restrict__ L1,
              __nv_bfloat16* __restrict__ H2, __nv_bfloat16* __restrict__ L2,
              int K, int N)
{
    constexpr int BM = 128, BN = 128, BK = 32, STR = 40;
    __shared__ __nv_bfloat16 As[2][BM * STR];
    __shared__ __nv_bfloat16 Bs[2][BN * STR];

    const int t = threadIdx.x;
    const int wid = t >> 5, lane = t & 31;
    const int warp_m = wid >> 2;
    const int warp_n = wid & 3;
    const int bm = blockIdx.y * BM;
    const int bn = blockIdx.x * BN;

    float acc[4][4][4];
    #pragma unroll
    for (int i = 0; i < 4; i++)
        #pragma unroll
        for (int j = 0; j < 4; j++)
            #pragma unroll
            for (int r = 0; r < 4; r++) acc[i][j][r] = 0.f;

    const uint32_t sA[2] = { smem_u32(As[0]), smem_u32(As[1]) };
    const uint32_t sB[2] = { smem_u32(Bs[0]), smem_u32(Bs[1]) };

    const int nkp = K / BK;
    const int nk = 3 * nkp;

    const int r0 = t >> 2, ch = (t & 3) * 8;
    const uint32_t soff0 = (uint32_t)(r0 * STR + ch) * 2;
    const uint32_t soff1 = (uint32_t)((r0 + 64) * STR + ch) * 2;

    auto issue = [&](int i) {
        const int s = i & 1;
        const int p = i / nkp;
        const int k0 = (i - p * nkp) * BK;
        const __nv_bfloat16* Ap = (p == 2) ? Alo : Ahi;
        const __nv_bfloat16* Bp = (p == 1) ? Blo : Bhi;
        CP_ASYNC16(sA[s] + soff0, Ap + (size_t)(bm + r0) * K + k0 + ch);
        CP_ASYNC16(sA[s] + soff1, Ap + (size_t)(bm + r0 + 64) * K + k0 + ch);
        CP_ASYNC16(sB[s] + soff0, Bp + (size_t)(bn + r0) * K + k0 + ch);
        CP_ASYNC16(sB[s] + soff1, Bp + (size_t)(bn + r0 + 64) * K + k0 + ch);
        CP_COMMIT();
    };

    issue(0);
    for (int i = 0; i < nk; i++) {
        CP_WAIT0();
        __syncthreads();
        if (i + 1 < nk) issue(i + 1);
        const int s = i & 1;

        #pragma unroll
        for (int ks = 0; ks < 2; ks++) {
            uint32_t a[4][4];
            uint32_t b[4][2];
            #pragma unroll
            for (int mt = 0; mt < 4; mt++) {
                const int row = warp_m * 64 + mt * 16 + (lane & 15);
                const int kc = ks * 16 + ((lane >> 4) * 8);
                ldm_x4(a[mt], sA[s] + (uint32_t)(row * STR + kc) * 2);
            }
            #pragma unroll
            for (int nt = 0; nt < 4; nt++) {
                const int row = warp_n * 32 + nt * 8 + (lane & 7);
                const int kc = ks * 16 + (((lane >> 3) & 1) * 8);
                ldm_x2(b[nt], sB[s] + (uint32_t)(row * STR + kc) * 2);
            }
            #pragma unroll
            for (int mt = 0; mt < 4; mt++)
                #pragma unroll
                for (int nt = 0; nt < 4; nt++)
                    mma16816(acc[mt][nt], a[mt], b[nt]);
        }
    }

    // Epilogue
    const int sec = bn >> 10;
    float* Fsec = nullptr;
    __nv_bfloat16 *Hsec = nullptr, *Lsec = nullptr;
    int cstride = N;
    if (SPLIT) {
        Fsec = (sec == 0) ? nullptr : ((sec == 1) ? F1 : F2);
        Hsec = (sec == 0) ? H0 : ((sec == 1) ? H1 : H2);
        Lsec = (sec == 0) ? L0 : ((sec == 1) ? L1 : L2);
        cstride = 1024;
    }

    #pragma unroll
    for (int mt = 0; mt < 4; mt++) {
        const int m0 = bm + warp_m * 64 + mt * 16 + (lane >> 2);
        #pragma unroll
        for (int nt = 0; nt < 4; nt++) {
            const int n0 = bn + warp_n * 32 + nt * 8 + (lane & 3) * 2;
            float b0 = 0.f, b1 = 0.f;
            if (bias) { b0 = bias[n0]; b1 = bias[n0 + 1]; }
            const int col = SPLIT ? (n0 & 1023) : n0;
            float2 v0 = { acc[mt][nt][0] + b0, acc[mt][nt][1] + b1 };
            float2 v1 = { acc[mt][nt][2] + b0, acc[mt][nt][3] + b1 };
            if (SPLIT) {
                if (Fsec) {
                    *(float2*)(Fsec + (size_t)m0 * cstride + col)       = v0;
                    *(float2*)(Fsec + (size_t)(m0 + 8) * cstride + col) = v1;
                }
                __nv_bfloat162 h0 = __float22bfloat162_rn(v0);
                __nv_bfloat162 l0;
                l0.x = __float2bfloat16_rn(v0.x - __bfloat162float(h0.x));
                l0.y = __float2bfloat16_rn(v0.y - __bfloat162float(h0.y));
                __nv_bfloat162 h1 = __float22bfloat162_rn(v1);
                __nv_bfloat162 l1;
                l1.x = __float2bfloat16_rn(v1.x - __bfloat162float(h1.x));
                l1.y = __float2bfloat16_rn(v1.y - __bfloat162float(h1.y));
                *(__nv_bfloat162*)(Hsec + (size_t)m0 * 1024 + col)       = h0;
                *(__nv_bfloat162*)(Lsec + (size_t)m0 * 1024 + col)       = l0;
                *(__nv_bfloat162*)(Hsec + (size_t)(m0 + 8) * 1024 + col) = h1;
                *(__nv_bfloat162*)(Lsec + (size_t)(m0 + 8) * 1024 + col) = l1;
            } else {
                *(float2*)(C0 + (size_t)m0 * cstride + col)       = v0;
                *(float2*)(C0 + (size_t)(m0 + 8) * cstride + col) = v1;
            }
        }
    }
}

// ---------------------------------------------------------------------------
// Flash attention on HMMA. CTA: 64 q-rows, 4 warps (16 rows each), KB=64.
// S = 3-pass split QK^T; softmax; PV = 3-pass split (P hi/lo, V hi/lo).
// Writes ctx fp32 AND ctx bf16 hi/lo (for projection).
// ---------------------------------------------------------------------------
__global__ __launch_bounds__(128)
void attn_mma(const __nv_bfloat16* __restrict__ Qh, const __nv_bfloat16* __restrict__ Ql,
              const __nv_bfloat16* __restrict__ Kh, const __nv_bfloat16* __restrict__ Kl,
              const __nv_bfloat16* __restrict__ Vh, const __nv_bfloat16* __restrict__ Vl,
              const float* __restrict__ mask, float* __restrict__ Ctx,
              __nv_bfloat16* __restrict__ Chi, __nv_bfloat16* __restrict__ Clo)
{
    constexpr int STR = 72;  // padded bf16 stride
    __shared__ __nv_bfloat16 sK[4][64 * STR];   // [0]=Kh(/Qh stage) [1]=Kl(/Ql) [2]=Vh [3]=Vl
    __shared__ float msk[64];

    const int b = blockIdx.z, h = blockIdx.y, qt = blockIdx.x;
    const int t = threadIdx.x, wid = t >> 5, lane = t & 31;
    const float scale = 0.125f;

    const uint32_t s0 = smem_u32(sK[0]);
    const uint32_t s1 = smem_u32(sK[1]);
    const uint32_t s2 = smem_u32(sK[2]);
    const uint32_t s3 = smem_u32(sK[3]);

    // ---- stage Q tile (64x64 hi/lo) and load fragments
    {
        const size_t qbase = (size_t)(b * SS + qt * 64) * HH + h * DHEAD;
        #pragma unroll
        for (int i = 0; i < 4; i++) {
            const int id = t + i * 128;
            const int r = id >> 3, c = (id & 7) * 8;
            *(uint4*)&sK[0][r * STR + c] = *(const uint4*)(Qh + qbase + (size_t)r * HH + c);
            *(uint4*)&sK[1][r * STR + c] = *(const uint4*)(Ql + qbase + (size_t)r * HH + c);
        }
    }
    __syncthreads();
    uint32_t qhf[4][4], qlf[4][4];
    {
        const int row = wid * 16 + (lane & 15);
        #pragma unroll
        for (int ks = 0; ks < 4; ks++) {
            const int kc = ks * 16 + ((lane >> 4) * 8);
            ldm_x4(qhf[ks], s0 + (uint32_t)(row * STR + kc) * 2);
            ldm_x4(qlf[ks], s1 + (uint32_t)(row * STR + kc) * 2);
        }
    }
    __syncthreads();

    // ---- flash state
    float o[8][4];
    #pragma unroll
    for (int nt = 0; nt < 8; nt++)
        #pragma unroll
        for (int r = 0; r < 4; r++) o[nt][r] = 0.f;
    float m0 = -INFINITY, m1 = -INFINITY;
    float l0 = 0.f, l1 = 0.f;

    for (int kt = 0; kt < SS / 64; kt++) {
        // load K/V hi/lo tiles
        {
            const size_t kbase = (size_t)(b * SS + kt * 64) * HH + h * DHEAD;
            #pragma unroll
            for (int i = 0; i < 4; i++) {
                const int id = t + i * 128;
                const int r = id >> 3, c = (id & 7) * 8;
                const size_t g = kbase + (size_t)r * HH + c;
                const uint32_t off = (uint32_t)(r * STR + c);
                *(uint4*)&sK[0][off] = *(const uint4*)(Kh + g);
                *(uint4*)&sK[1][off] = *(const uint4*)(Kl + g);
                *(uint4*)&sK[2][off] = *(const uint4*)(Vh + g);
                *(uint4*)&sK[3][off] = *(const uint4*)(Vl + g);
            }
            if (t < 64) msk[t] = mask[b * SS + kt * 64 + t];
        }
        __syncthreads();

        // ---- S = Qh@Kh^T + Qh@Kl^T + Ql@Kh^T  (16 x 64 per warp)
        float sacc[8][4];
        #pragma unroll
        for (int nt = 0; nt < 8; nt++)
            #pragma unroll
            for (int r = 0; r < 4; r++) sacc[nt][r] = 0.f;

        #pragma unroll
        for (int ks = 0; ks < 4; ks++) {
            #pragma unroll
            for (int nt = 0; nt < 8; nt++) {
                uint32_t bh[2], bl[2];
                const int row = nt * 8 + (lane & 7);
                const int kc = ks * 16 + (((lane >> 3) & 1) * 8);
                const uint32_t off = (uint32_t)(row * STR + kc) * 2;
                ldm_x2(bh, s0 + off);
                ldm_x2(bl, s1 + off);
                mma16816(sacc[nt], qhf[ks], bh);
                mma16816(sacc[nt], qhf[ks], bl);
                mma16816(sacc[nt], qlf[ks], bh);
            }
        }

        // ---- softmax (rows r=lane/4 and r+8; cols per nt: nt*8+(lane&3)*2,+1)
        float nm0 = m0, nm1 = m1;
        #pragma unroll
        for (int nt = 0; nt < 8; nt++) {
            const int c0 = nt * 8 + (lane & 3) * 2;
            const float mk0 = msk[c0], mk1 = msk[c0 + 1];
            sacc[nt][0] = sacc[nt][0] * scale + mk0;
            sacc[nt][1] = sacc[nt][1] * scale + mk1;
            sacc[nt][2] = sacc[nt][2] * scale + mk0;
            sacc[nt][3] = sacc[nt][3] * scale + mk1;
            nm0 = fmaxf(nm0, fmaxf(sacc[nt][0], sacc[nt][1]));
            nm1 = fmaxf(nm1, fmaxf(sacc[nt][2], sacc[nt][3]));
        }
        nm0 = fmaxf(nm0, __shfl_xor_sync(0xFFFFFFFFu, nm0, 1));
        nm0 = fmaxf(nm0, __shfl_xor_sync(0xFFFFFFFFu, nm0, 2));
        nm1 = fmaxf(nm1, __shfl_xor_sync(0xFFFFFFFFu, nm1, 1));
        nm1 = fmaxf(nm1, __shfl_xor_sync(0xFFFFFFFFu, nm1, 2));

        const float cr0 = __expf(m0 - nm0);
        const float cr1 = __expf(m1 - nm1);
        l0 *= cr0; l1 *= cr1;
        #pragma unroll
        for (int nt = 0; nt < 8; nt++) {
            o[nt][0] *= cr0; o[nt][1] *= cr0;
            o[nt][2] *= cr1; o[nt][3] *= cr1;
        }
        #pragma unroll
        for (int nt = 0; nt < 8; nt++) {
            sacc[nt][0] = __expf(sacc[nt][0] - nm0);
            sacc[nt][1] = __expf(sacc[nt][1] - nm0);
            sacc[nt][2] = __expf(sacc[nt][2] - nm1);
            sacc[nt][3] = __expf(sacc[nt][3] - nm1);
            l0 += sacc[nt][0] + sacc[nt][1];
            l1 += sacc[nt][2] + sacc[nt][3];
        }
        m0 = nm0; m1 = nm1;

        // ---- PV: for each k-step, P A-frag from S n-tiles (2ks, 2ks+1)
        #pragma unroll
        for (int ks = 0; ks < 4; ks++) {
            uint32_t ph[4], pl[4];
            {
                const float* sa = sacc[2 * ks];
                const float* sb = sacc[2 * ks + 1];
                __nv_bfloat162 h, l;
                float2 f;
                f.x = sa[0]; f.y = sa[1];
                h = __float22bfloat162_rn(f);
                l.x = __float2bfloat16_rn(f.x - __bfloat162float(h.x));
                l.y = __float2bfloat16_rn(f.y - __bfloat162float(h.y));
                ph[0] = *(uint32_t*)&h; pl[0] = *(uint32_t*)&l;
                f.x = sa[2]; f.y = sa[3];
                h = __float22bfloat162_rn(f);
                l.x = __float2bfloat16_rn(f.x - __bfloat162float(h.x));
                l.y = __float2bfloat16_rn(f.y - __bfloat162float(h.y));
                ph[1] = *(uint32_t*)&h; pl[1] = *(uint32_t*)&l;
                f.x = sb[0]; f.y = sb[1];
                h = __float22bfloat162_rn(f);
                l.x = __float2bfloat16_rn(f.x - __bfloat162float(h.x));
                l.y = __float2bfloat16_rn(f.y - __bfloat162float(h.y));
                ph[2] = *(uint32_t*)&h; pl[2] = *(uint32_t*)&l;
                f.x = sb[2]; f.y = sb[3];
                h = __float22bfloat162_rn(f);
                l.x = __float2bfloat16_rn(f.x - __bfloat162float(h.x));
                l.y = __float2bfloat16_rn(f.y - __bfloat162float(h.y));
                ph[3] = *(uint32_t*)&h; pl[3] = *(uint32_t*)&l;
            }
            #pragma unroll
            for (int nt = 0; nt < 8; nt++) {
                uint32_t vh[2], vl[2];
                const int row = ks * 16 + (lane & 7) + (((lane >> 3) & 1) * 8);
                const uint32_t off = (uint32_t)(row * STR + nt * 8) * 2;
                ldm_x2t(vh, s2 + off);
                ldm_x2t(vl, s3 + off);
                mma16816(o[nt], ph, vh);
                mma16816(o[nt], ph, vl);
                mma16816(o[nt], pl, vh);
            }
        }
        __syncthreads();
    }

    // ---- final reduce + write
    l0 += __shfl_xor_sync(0xFFFFFFFFu, l0, 1);
    l0 += __shfl_xor_sync(0xFFFFFFFFu, l0, 2);
    l1 += __shfl_xor_sync(0xFFFFFFFFu, l1, 1);
    l1 += __shfl_xor_sync(0xFFFFFFFFu, l1, 2);
    const float inv0 = 1.0f / l0;
    const float inv1 = 1.0f / l1;

    const int grow0 = b * SS + qt * 64 + wid * 16 + (lane >> 2);
    const int grow1 = grow0 + 8;
    #pragma unroll
    for (int nt = 0; nt < 8; nt++) {
        const int col = h * DHEAD + nt * 8 + (lane & 3) * 2;
        float2 v0 = { o[nt][0] * inv0, o[nt][1] * inv0 };
        float2 v1 = { o[nt][2] * inv1, o[nt][3] * inv1 };
        *(float2*)(Ctx + (size_t)grow0 * HH + col) = v0;
        *(float2*)(Ctx + (size_t)grow1 * HH + col) = v1;
        __nv_bfloat162 h0 = __float22bfloat162_rn(v0);
        __nv_bfloat162 l0b;
        l0b.x = __float2bfloat16_rn(v0.x - __bfloat162float(h0.x));
        l0b.y = __float2bfloat16_rn(v0.y - __bfloat162float(h0.y));
        __nv_bfloat162 h1 = __float22bfloat162_rn(v1);
        __nv_bfloat162 l1b;
        l1b.x = __float2bfloat16_rn(v1.x - __bfloat162float(h1.x));
        l1b.y = __float2bfloat16_rn(v1.y - __bfloat162float(h1.y));
        *(__nv_bfloat162*)(Chi + (size_t)grow0 * HH + col) = h0;
        *(__nv_bfloat162*)(Clo + (size_t)grow0 * HH + col) = l0b;
        *(__nv_bfloat162*)(Chi + (size_t)grow1 * HH + col) = h1;
        *(__nv_bfloat162*)(Clo + (size_t)grow1 * HH + col) = l1b;
    }
}

// ---------------------------------------------------------------------------
// Launch
// ---------------------------------------------------------------------------
extern "C" void kernel_launch(void* const* d_in, const int* in_sizes, int n_in,
                              void* d_out, int out_size)
{
    const float* input = (const float*)d_in[0];
    const float* mask  = (const float*)d_in[1];
    const float* nw    = (const float*)d_in[2];
    const float* nb    = (const float*)d_in[3];
    const float* qkvw  = (const float*)d_in[4];
    const float* qkvb  = (const float*)d_in[5];
    const float* ow    = (const float*)d_in[6];

    float* out     = (float*)d_out;
    float* key_out = out + (size_t)TENSOR_ELEMS;
    float* val_out = out + (size_t)2 * TENSOR_ELEMS;
    float* ctx_out = out + (size_t)3 * TENSOR_ELEMS;

    __nv_bfloat16 *a_hi, *a_lo, *w_hi, *w_lo, *ow_hi, *ow_lo;
    __nv_bfloat16 *q_hi, *q_lo, *k_hi, *k_lo, *v_hi, *v_lo, *c_hi, *c_lo;
    cudaGetSymbolAddress((void**)&a_hi, g_a_hi);
    cudaGetSymbolAddress((void**)&a_lo, g_a_lo);
    cudaGetSymbolAddress((void**)&w_hi, g_w_hi);
    cudaGetSymbolAddress((void**)&w_lo, g_w_lo);
    cudaGetSymbolAddress((void**)&ow_hi, g_ow_hi);
    cudaGetSymbolAddress((void**)&ow_lo, g_ow_lo);
    cudaGetSymbolAddress((void**)&q_hi, g_q_hi);
    cudaGetSymbolAddress((void**)&q_lo, g_q_lo);
    cudaGetSymbolAddress((void**)&k_hi, g_k_hi);
    cudaGetSymbolAddress((void**)&k_lo, g_k_lo);
    cudaGetSymbolAddress((void**)&v_hi, g_v_hi);
    cudaGetSymbolAddress((void**)&v_lo, g_v_lo);
    cudaGetSymbolAddress((void**)&c_hi, g_c_hi);
    cudaGetSymbolAddress((void**)&c_lo, g_c_lo);

    // 1) LayerNorm -> bf16 split
    ln_kernel<<<MROWS, 256>>>(input, nw, nb, a_hi, a_lo);

    // 2) Weight splits
    split_kernel<<<(3 * HH * HH / 4 + 255) / 256, 256>>>(qkvw, w_hi, w_lo, 3 * HH * HH / 4);
    split_kernel<<<(HH * HH / 4 + 255) / 256, 256>>>(ow, ow_hi, ow_lo, HH * HH / 4);

    // 3) QKV GEMM: fp32 K/V outputs + bf16 hi/lo Q/K/V scratch
    {
        dim3 grid(3072 / 128, MROWS / 128);
        gemm_mma<true><<<grid, 256>>>(a_hi, a_lo, w_hi, w_lo, qkvb,
                                      key_out, val_out, nullptr,
                                      q_hi, q_lo, k_hi, k_lo, v_hi, v_lo,
                                      HH, 3 * HH);
    }

    // 4) Flash attention (HMMA) -> ctx fp32 + ctx bf16 hi/lo
    {
        dim3 grid(SS / 64, NHEADS, BB);
        attn_mma<<<grid, 128>>>(q_hi, q_lo, k_hi, k_lo, v_hi, v_lo,
                                mask, ctx_out, c_hi, c_lo);
    }

    // 5) Output projection
    {
        dim3 grid(HH / 128, MROWS / 128);
        gemm_mma<false><<<grid, 256>>>(c_hi, c_lo, ow_hi, ow_lo, nullptr,
                                       nullptr, nullptr, out,
                                       nullptr, nullptr, nullptr, nullptr, nullptr, nullptr,
                                       HH, HH);
    }
}

// round 9
// speedup vs baseline: 2.7845x; 1.0009x over previous
#include <cuda_runtime.h>
#include <cuda_bf16.h>
#include <math.h>
#include <stdint.h>

// Problem constants (fixed by the reference)
#define BB 4
#define SS 2048
#define HH 1024
#define NHEADS 16
#define DHEAD 64
#define MROWS (BB * SS)            // 8192
#define TENSOR_ELEMS (MROWS * HH)  // 8,388,608 per output tensor

// ---------------------------------------------------------------------------
// Scratch (__device__ globals; no runtime allocation allowed)
// ---------------------------------------------------------------------------
__device__ __nv_bfloat16 g_a_hi[MROWS * HH];
__device__ __nv_bfloat16 g_a_lo[MROWS * HH];
__device__ __nv_bfloat16 g_w_hi[3 * HH * HH];
__device__ __nv_bfloat16 g_w_lo[3 * HH * HH];
__device__ __nv_bfloat16 g_ow_hi[HH * HH];
__device__ __nv_bfloat16 g_ow_lo[HH * HH];
__device__ __nv_bfloat16 g_q_hi[MROWS * HH];
__device__ __nv_bfloat16 g_q_lo[MROWS * HH];
__device__ __nv_bfloat16 g_k_hi[MROWS * HH];
__device__ __nv_bfloat16 g_k_lo[MROWS * HH];
__device__ __nv_bfloat16 g_v_hi[MROWS * HH];
__device__ __nv_bfloat16 g_v_lo[MROWS * HH];
__device__ __nv_bfloat16 g_c_hi[MROWS * HH];
__device__ __nv_bfloat16 g_c_lo[MROWS * HH];

// ---------------------------------------------------------------------------
// PTX helpers — target-portable (sm_80+)
// ---------------------------------------------------------------------------
__device__ __forceinline__ uint32_t smem_u32(const void* p) {
    uint32_t a;
    asm("{ .reg .u64 t; cvta.to.shared.u64 t, %1; cvt.u32.u64 %0, t; }" : "=r"(a) : "l"(p));
    return a;
}
#define CP_ASYNC16(dst, src) \
    asm volatile("cp.async.cg.shared.global [%0], [%1], 16;" :: "r"(dst), "l"(src))
#define CP_COMMIT() asm volatile("cp.async.commit_group;" ::: "memory")
#define CP_WAIT0()  asm volatile("cp.async.wait_group 0;" ::: "memory")

__device__ __forceinline__ void ldm_x4(uint32_t* r, uint32_t addr) {
    asm volatile("ldmatrix.sync.aligned.m8n8.x4.shared.b16 {%0,%1,%2,%3}, [%4];"
                 : "=r"(r[0]), "=r"(r[1]), "=r"(r[2]), "=r"(r[3]) : "r"(addr));
}
__device__ __forceinline__ void ldm_x2(uint32_t* r, uint32_t addr) {
    asm volatile("ldmatrix.sync.aligned.m8n8.x2.shared.b16 {%0,%1}, [%2];"
                 : "=r"(r[0]), "=r"(r[1]) : "r"(addr));
}
__device__ __forceinline__ void ldm_x2t(uint32_t* r, uint32_t addr) {
    asm volatile("ldmatrix.sync.aligned.m8n8.x2.trans.shared.b16 {%0,%1}, [%2];"
                 : "=r"(r[0]), "=r"(r[1]) : "r"(addr));
}
__device__ __forceinline__ void mma16816(float* c, const uint32_t* a, const uint32_t* b) {
    asm volatile(
        "mma.sync.aligned.m16n8k16.row.col.f32.bf16.bf16.f32 "
        "{%0,%1,%2,%3}, {%4,%5,%6,%7}, {%8,%9}, {%0,%1,%2,%3};"
        : "+f"(c[0]), "+f"(c[1]), "+f"(c[2]), "+f"(c[3])
        : "r"(a[0]), "r"(a[1]), "r"(a[2]), "r"(a[3]), "r"(b[0]), "r"(b[1]));
}

// ---------------------------------------------------------------------------
// Kernel 1: LayerNorm -> bf16 hi/lo split. One block per row, 256 threads.
// ---------------------------------------------------------------------------
__global__ __launch_bounds__(256)
void ln_kernel(const float* __restrict__ x,
               const float* __restrict__ w,
               const float* __restrict__ bvec,
               __nv_bfloat16* __restrict__ yhi,
               __nv_bfloat16* __restrict__ ylo)
{
    const int row = blockIdx.x;
    const int t = threadIdx.x;
    const float4 xv = ((const float4*)(x + (size_t)row * HH))[t];

    float s  = xv.x + xv.y + xv.z + xv.w;
    float ss = xv.x * xv.x + xv.y * xv.y + xv.z * xv.z + xv.w * xv.w;
    #pragma unroll
    for (int o = 16; o > 0; o >>= 1) {
        s  += __shfl_xor_sync(0xFFFFFFFFu, s,  o);
        ss += __shfl_xor_sync(0xFFFFFFFFu, ss, o);
    }
    __shared__ float rs[8], rss[8];
    __shared__ float smu, srstd;
    const int wid = t >> 5, lane = t & 31;
    if (lane == 0) { rs[wid] = s; rss[wid] = ss; }
    __syncthreads();
    if (t == 0) {
        float a = 0.f, b2 = 0.f;
        #pragma unroll
        for (int i = 0; i < 8; i++) { a += rs[i]; b2 += rss[i]; }
        const float mu = a * (1.0f / HH);
        float var = b2 * (1.0f / HH) - mu * mu;
        smu = mu;
        srstd = rsqrtf(var + 1e-12f);
    }
    __syncthreads();
    const float mu = smu, rstd = srstd;
    const float4 wv = ((const float4*)w)[t];
    const float4 bv = ((const float4*)bvec)[t];
    float v[4];
    v[0] = (xv.x - mu) * rstd * wv.x + bv.x;
    v[1] = (xv.y - mu) * rstd * wv.y + bv.y;
    v[2] = (xv.z - mu) * rstd * wv.z + bv.z;
    v[3] = (xv.w - mu) * rstd * wv.w + bv.w;
    __nv_bfloat16 hi[4], lo[4];
    #pragma unroll
    for (int i = 0; i < 4; i++) {
        hi[i] = __float2bfloat16_rn(v[i]);
        lo[i] = __float2bfloat16_rn(v[i] - __bfloat162float(hi[i]));
    }
    const size_t base = (size_t)row * HH + t * 4;
    *(uint64_t*)(yhi + base) = *(uint64_t*)hi;
    *(uint64_t*)(ylo + base) = *(uint64_t*)lo;
}

// ---------------------------------------------------------------------------
// Kernel: fp32 -> bf16 hi/lo split (weights)
// ---------------------------------------------------------------------------
__global__ __launch_bounds__(256)
void split_kernel(const float* __restrict__ x,
                  __nv_bfloat16* __restrict__ hi,
                  __nv_bfloat16* __restrict__ lo, int n4)
{
    const int i = blockIdx.x * 256 + threadIdx.x;
    if (i >= n4) return;
    const float4 v = ((const float4*)x)[i];
    __nv_bfloat16 h[4], l[4];
    const float vv[4] = {v.x, v.y, v.z, v.w};
    #pragma unroll
    for (int j = 0; j < 4; j++) {
        h[j] = __float2bfloat16_rn(vv[j]);
        l[j] = __float2bfloat16_rn(vv[j] - __bfloat162float(h[j]));
    }
    ((uint64_t*)hi)[i] = *(uint64_t*)h;
    ((uint64_t*)lo)[i] = *(uint64_t*)l;
}

// ---------------------------------------------------------------------------
// bf16 3-pass split GEMM (HMMA). SPLIT: per-section fp32 + bf16 hi/lo outputs.
// ---------------------------------------------------------------------------
template<bool SPLIT>
__global__ __launch_bounds__(256)
void gemm_mma(const __nv_bfloat16* __restrict__ Ahi, const __nv_bfloat16* __restrict__ Alo,
              const __nv_bfloat16* __restrict__ Bhi, const __nv_bfloat16* __restrict__ Blo,
              const float* __restrict__ bias,
              float* __restrict__ F1, float* __restrict__ F2,      // key/value fp32
              float* __restrict__ C0,                              // plain output (non-split)
              __nv_bfloat16* __restrict__ H0, __nv_bfloat16* __restrict__ L0,
              __nv_bfloat16* __restrict__ H1, __nv_bfloat16* __restrict__ L1,
              __nv_bfloat16* __restrict__ H2, __nv_bfloat16* __restrict__ L2,
              int K, int N)
{
    constexpr int BM = 128, BN = 128, BK = 32, STR = 40;
    __shared__ __nv_bfloat16 As[2][BM * STR];
    __shared__ __nv_bfloat16 Bs[2][BN * STR];

    const int t = threadIdx.x;
    const int wid = t >> 5, lane = t & 31;
    const int warp_m = wid >> 2;
    const int warp_n = wid & 3;
    const int bm = blockIdx.y * BM;
    const int bn = blockIdx.x * BN;

    float acc[4][4][4];
    #pragma unroll
    for (int i = 0; i < 4; i++)
        #pragma unroll
        for (int j = 0; j < 4; j++)
            #pragma unroll
            for (int r = 0; r < 4; r++) acc[i][j][r] = 0.f;

    const uint32_t sA[2] = { smem_u32(As[0]), smem_u32(As[1]) };
    const uint32_t sB[2] = { smem_u32(Bs[0]), smem_u32(Bs[1]) };

    const int nkp = K / BK;
    const int nk = 3 * nkp;

    const int r0 = t >> 2, ch = (t & 3) * 8;
    const uint32_t soff0 = (uint32_t)(r0 * STR + ch) * 2;
    const uint32_t soff1 = (uint32_t)((r0 + 64) * STR + ch) * 2;

    auto issue = [&](int i) {
        const int s = i & 1;
        const int p = i / nkp;
        const int k0 = (i - p * nkp) * BK;
        const __nv_bfloat16* Ap = (p == 2) ? Alo : Ahi;
        const __nv_bfloat16* Bp = (p == 1) ? Blo : Bhi;
        CP_ASYNC16(sA[s] + soff0, Ap + (size_t)(bm + r0) * K + k0 + ch);
        CP_ASYNC16(sA[s] + soff1, Ap + (size_t)(bm + r0 + 64) * K + k0 + ch);
        CP_ASYNC16(sB[s] + soff0, Bp + (size_t)(bn + r0) * K + k0 + ch);
        CP_ASYNC16(sB[s] + soff1, Bp + (size_t)(bn + r0 + 64) * K + k0 + ch);
        CP_COMMIT();
    };

    issue(0);
    for (int i = 0; i < nk; i++) {
        CP_WAIT0();
        __syncthreads();
        if (i + 1 < nk) issue(i + 1);
        const int s = i & 1;

        #pragma unroll
        for (int ks = 0; ks < 2; ks++) {
            uint32_t a[4][4];
            uint32_t b[4][2];
            #pragma unroll
            for (int mt = 0; mt < 4; mt++) {
                const int row = warp_m * 64 + mt * 16 + (lane & 15);
                const int kc = ks * 16 + ((lane >> 4) * 8);
                ldm_x4(a[mt], sA[s] + (uint32_t)(row * STR + kc) * 2);
            }
            #pragma unroll
            for (int nt = 0; nt < 4; nt++) {
                const int row = warp_n * 32 + nt * 8 + (lane & 7);
                const int kc = ks * 16 + (((lane >> 3) & 1) * 8);
                ldm_x2(b[nt], sB[s] + (uint32_t)(row * STR + kc) * 2);
            }
            #pragma unroll
            for (int mt = 0; mt < 4; mt++)
                #pragma unroll
                for (int nt = 0; nt < 4; nt++)
                    mma16816(acc[mt][nt], a[mt], b[nt]);
        }
    }

    // Epilogue
    const int sec = bn >> 10;
    float* Fsec = nullptr;
    __nv_bfloat16 *Hsec = nullptr, *Lsec = nullptr;
    int cstride = N;
    if (SPLIT) {
        Fsec = (sec == 0) ? nullptr : ((sec == 1) ? F1 : F2);
        Hsec = (sec == 0) ? H0 : ((sec == 1) ? H1 : H2);
        Lsec = (sec == 0) ? L0 : ((sec == 1) ? L1 : L2);
        cstride = 1024;
    }

    #pragma unroll
    for (int mt = 0; mt < 4; mt++) {
        const int m0 = bm + warp_m * 64 + mt * 16 + (lane >> 2);
        #pragma unroll
        for (int nt = 0; nt < 4; nt++) {
            const int n0 = bn + warp_n * 32 + nt * 8 + (lane & 3) * 2;
            float b0 = 0.f, b1 = 0.f;
            if (bias) { b0 = bias[n0]; b1 = bias[n0 + 1]; }
            const int col = SPLIT ? (n0 & 1023) : n0;
            float2 v0 = { acc[mt][nt][0] + b0, acc[mt][nt][1] + b1 };
            float2 v1 = { acc[mt][nt][2] + b0, acc[mt][nt][3] + b1 };
            if (SPLIT) {
                if (Fsec) {
                    *(float2*)(Fsec + (size_t)m0 * cstride + col)       = v0;
                    *(float2*)(Fsec + (size_t)(m0 + 8) * cstride + col) = v1;
                }
                __nv_bfloat162 h0 = __float22bfloat162_rn(v0);
                __nv_bfloat162 l0;
                l0.x = __float2bfloat16_rn(v0.x - __bfloat162float(h0.x));
                l0.y = __float2bfloat16_rn(v0.y - __bfloat162float(h0.y));
                __nv_bfloat162 h1 = __float22bfloat162_rn(v1);
                __nv_bfloat162 l1;
                l1.x = __float2bfloat16_rn(v1.x - __bfloat162float(h1.x));
                l1.y = __float2bfloat16_rn(v1.y - __bfloat162float(h1.y));
                *(__nv_bfloat162*)(Hsec + (size_t)m0 * 1024 + col)       = h0;
                *(__nv_bfloat162*)(Lsec + (size_t)m0 * 1024 + col)       = l0;
                *(__nv_bfloat162*)(Hsec + (size_t)(m0 + 8) * 1024 + col) = h1;
                *(__nv_bfloat162*)(Lsec + (size_t)(m0 + 8) * 1024 + col) = l1;
            } else {
                *(float2*)(C0 + (size_t)m0 * cstride + col)       = v0;
                *(float2*)(C0 + (size_t)(m0 + 8) * cstride + col) = v1;
            }
        }
    }
}

// ---------------------------------------------------------------------------
// Flash attention on HMMA. CTA: 64 q-rows, 4 warps (16 rows each), KB=64.
// S = 3-pass split QK^T; softmax; PV = 3-pass split (P hi/lo, V hi/lo).
// Writes ctx fp32 AND ctx bf16 hi/lo (for projection).
// ---------------------------------------------------------------------------
__global__ __launch_bounds__(128)
void attn_mma(const __nv_bfloat16* __restrict__ Qh, const __nv_bfloat16* __restrict__ Ql,
              const __nv_bfloat16* __restrict__ Kh, const __nv_bfloat16* __restrict__ Kl,
              const __nv_bfloat16* __restrict__ Vh, const __nv_bfloat16* __restrict__ Vl,
              const float* __restrict__ mask, float* __restrict__ Ctx,
              __nv_bfloat16* __restrict__ Chi, __nv_bfloat16* __restrict__ Clo)
{
    constexpr int STR = 72;  // padded bf16 stride
    __shared__ __nv_bfloat16 sK[4][64 * STR];   // [0]=Kh(/Qh stage) [1]=Kl(/Ql) [2]=Vh [3]=Vl
    __shared__ float msk[64];

    const int b = blockIdx.z, h = blockIdx.y, qt = blockIdx.x;
    const int t = threadIdx.x, wid = t >> 5, lane = t & 31;
    const float scale = 0.125f;

    const uint32_t s0 = smem_u32(sK[0]);
    const uint32_t s1 = smem_u32(sK[1]);
    const uint32_t s2 = smem_u32(sK[2]);
    const uint32_t s3 = smem_u32(sK[3]);

    // ---- stage Q tile (64x64 hi/lo) and load fragments
    {
        const size_t qbase = (size_t)(b * SS + qt * 64) * HH + h * DHEAD;
        #pragma unroll
        for (int i = 0; i < 4; i++) {
            const int id = t + i * 128;
            const int r = id >> 3, c = (id & 7) * 8;
            *(uint4*)&sK[0][r * STR + c] = *(const uint4*)(Qh + qbase + (size_t)r * HH + c);
            *(uint4*)&sK[1][r * STR + c] = *(const uint4*)(Ql + qbase + (size_t)r * HH + c);
        }
    }
    __syncthreads();
    uint32_t qhf[4][4], qlf[4][4];
    {
        const int row = wid * 16 + (lane & 15);
        #pragma unroll
        for (int ks = 0; ks < 4; ks++) {
            const int kc = ks * 16 + ((lane >> 4) * 8);
            ldm_x4(qhf[ks], s0 + (uint32_t)(row * STR + kc) * 2);
            ldm_x4(qlf[ks], s1 + (uint32_t)(row * STR + kc) * 2);
        }
    }
    __syncthreads();

    // ---- flash state
    float o[8][4];
    #pragma unroll
    for (int nt = 0; nt < 8; nt++)
        #pragma unroll
        for (int r = 0; r < 4; r++) o[nt][r] = 0.f;
    float m0 = -INFINITY, m1 = -INFINITY;
    float l0 = 0.f, l1 = 0.f;

    for (int kt = 0; kt < SS / 64; kt++) {
        // load K/V hi/lo tiles
        {
            const size_t kbase = (size_t)(b * SS + kt * 64) * HH + h * DHEAD;
            #pragma unroll
            for (int i = 0; i < 4; i++) {
                const int id = t + i * 128;
                const int r = id >> 3, c = (id & 7) * 8;
                const size_t g = kbase + (size_t)r * HH + c;
                const uint32_t off = (uint32_t)(r * STR + c);
                *(uint4*)&sK[0][off] = *(const uint4*)(Kh + g);
                *(uint4*)&sK[1][off] = *(const uint4*)(Kl + g);
                *(uint4*)&sK[2][off] = *(const uint4*)(Vh + g);
                *(uint4*)&sK[3][off] = *(const uint4*)(Vl + g);
            }
            if (t < 64) msk[t] = mask[b * SS + kt * 64 + t];
        }
        __syncthreads();

        // ---- S = Qh@Kh^T + Qh@Kl^T + Ql@Kh^T  (16 x 64 per warp)
        float sacc[8][4];
        #pragma unroll
        for (int nt = 0; nt < 8; nt++)
            #pragma unroll
            for (int r = 0; r < 4; r++) sacc[nt][r] = 0.f;

        #pragma unroll
        for (int ks = 0; ks < 4; ks++) {
            #pragma unroll
            for (int nt = 0; nt < 8; nt++) {
                uint32_t bh[2], bl[2];
                const int row = nt * 8 + (lane & 7);
                const int kc = ks * 16 + (((lane >> 3) & 1) * 8);
                const uint32_t off = (uint32_t)(row * STR + kc) * 2;
                ldm_x2(bh, s0 + off);
                ldm_x2(bl, s1 + off);
                mma16816(sacc[nt], qhf[ks], bh);
                mma16816(sacc[nt], qhf[ks], bl);
                mma16816(sacc[nt], qlf[ks], bh);
            }
        }

        // ---- softmax (rows r=lane/4 and r+8; cols per nt: nt*8+(lane&3)*2,+1)
        float nm0 = m0, nm1 = m1;
        #pragma unroll
        for (int nt = 0; nt < 8; nt++) {
            const int c0 = nt * 8 + (lane & 3) * 2;
            const float mk0 = msk[c0], mk1 = msk[c0 + 1];
            sacc[nt][0] = sacc[nt][0] * scale + mk0;
            sacc[nt][1] = sacc[nt][1] * scale + mk1;
            sacc[nt][2] = sacc[nt][2] * scale + mk0;
            sacc[nt][3] = sacc[nt][3] * scale + mk1;
            nm0 = fmaxf(nm0, fmaxf(sacc[nt][0], sacc[nt][1]));
            nm1 = fmaxf(nm1, fmaxf(sacc[nt][2], sacc[nt][3]));
        }
        nm0 = fmaxf(nm0, __shfl_xor_sync(0xFFFFFFFFu, nm0, 1));
        nm0 = fmaxf(nm0, __shfl_xor_sync(0xFFFFFFFFu, nm0, 2));
        nm1 = fmaxf(nm1, __shfl_xor_sync(0xFFFFFFFFu, nm1, 1));
        nm1 = fmaxf(nm1, __shfl_xor_sync(0xFFFFFFFFu, nm1, 2));

        const float cr0 = __expf(m0 - nm0);
        const float cr1 = __expf(m1 - nm1);
        l0 *= cr0; l1 *= cr1;
        #pragma unroll
        for (int nt = 0; nt < 8; nt++) {
            o[nt][0] *= cr0; o[nt][1] *= cr0;
            o[nt][2] *= cr1; o[nt][3] *= cr1;
        }
        #pragma unroll
        for (int nt = 0; nt < 8; nt++) {
            sacc[nt][0] = __expf(sacc[nt][0] - nm0);
            sacc[nt][1] = __expf(sacc[nt][1] - nm0);
            sacc[nt][2] = __expf(sacc[nt][2] - nm1);
            sacc[nt][3] = __expf(sacc[nt][3] - nm1);
            l0 += sacc[nt][0] + sacc[nt][1];
            l1 += sacc[nt][2] + sacc[nt][3];
        }
        m0 = nm0; m1 = nm1;

        // ---- PV: for each k-step, P A-frag from S n-tiles (2ks, 2ks+1)
        #pragma unroll
        for (int ks = 0; ks < 4; ks++) {
            uint32_t ph[4], pl[4];
            {
                const float* sa = sacc[2 * ks];
                const float* sb = sacc[2 * ks + 1];
                __nv_bfloat162 h, l;
                float2 f;
                f.x = sa[0]; f.y = sa[1];
                h = __float22bfloat162_rn(f);
                l.x = __float2bfloat16_rn(f.x - __bfloat162float(h.x));
                l.y = __float2bfloat16_rn(f.y - __bfloat162float(h.y));
                ph[0] = *(uint32_t*)&h; pl[0] = *(uint32_t*)&l;
                f.x = sa[2]; f.y = sa[3];
                h = __float22bfloat162_rn(f);
                l.x = __float2bfloat16_rn(f.x - __bfloat162float(h.x));
                l.y = __float2bfloat16_rn(f.y - __bfloat162float(h.y));
                ph[1] = *(uint32_t*)&h; pl[1] = *(uint32_t*)&l;
                f.x = sb[0]; f.y = sb[1];
                h = __float22bfloat162_rn(f);
                l.x = __float2bfloat16_rn(f.x - __bfloat162float(h.x));
                l.y = __float2bfloat16_rn(f.y - __bfloat162float(h.y));
                ph[2] = *(uint32_t*)&h; pl[2] = *(uint32_t*)&l;
                f.x = sb[2]; f.y = sb[3];
                h = __float22bfloat162_rn(f);
                l.x = __float2bfloat16_rn(f.x - __bfloat162float(h.x));
                l.y = __float2bfloat16_rn(f.y - __bfloat162float(h.y));
                ph[3] = *(uint32_t*)&h; pl[3] = *(uint32_t*)&l;
            }
            #pragma unroll
            for (int nt = 0; nt < 8; nt++) {
                uint32_t vh[2], vl[2];
                const int row = ks * 16 + (lane & 7) + (((lane >> 3) & 1) * 8);
                const uint32_t off = (uint32_t)(row * STR + nt * 8) * 2;
                ldm_x2t(vh, s2 + off);
                ldm_x2t(vl, s3 + off);
                mma16816(o[nt], ph, vh);
                mma16816(o[nt], ph, vl);
                mma16816(o[nt], pl, vh);
            }
        }
        __syncthreads();
    }

    // ---- final reduce + write
    l0 += __shfl_xor_sync(0xFFFFFFFFu, l0, 1);
    l0 += __shfl_xor_sync(0xFFFFFFFFu, l0, 2);
    l1 += __shfl_xor_sync(0xFFFFFFFFu, l1, 1);
    l1 += __shfl_xor_sync(0xFFFFFFFFu, l1, 2);
    const float inv0 = 1.0f / l0;
    const float inv1 = 1.0f / l1;

    const int grow0 = b * SS + qt * 64 + wid * 16 + (lane >> 2);
    const int grow1 = grow0 + 8;
    #pragma unroll
    for (int nt = 0; nt < 8; nt++) {
        const int col = h * DHEAD + nt * 8 + (lane & 3) * 2;
        float2 v0 = { o[nt][0] * inv0, o[nt][1] * inv0 };
        float2 v1 = { o[nt][2] * inv1, o[nt][3] * inv1 };
        *(float2*)(Ctx + (size_t)grow0 * HH + col) = v0;
        *(float2*)(Ctx + (size_t)grow1 * HH + col) = v1;
        __nv_bfloat162 h0 = __float22bfloat162_rn(v0);
        __nv_bfloat162 l0b;
        l0b.x = __float2bfloat16_rn(v0.x - __bfloat162float(h0.x));
        l0b.y = __float2bfloat16_rn(v0.y - __bfloat162float(h0.y));
        __nv_bfloat162 h1 = __float22bfloat162_rn(v1);
        __nv_bfloat162 l1b;
        l1b.x = __float2bfloat16_rn(v1.x - __bfloat162float(h1.x));
        l1b.y = __float2bfloat16_rn(v1.y - __bfloat162float(h1.y));
        *(__nv_bfloat162*)(Chi + (size_t)grow0 * HH + col) = h0;
        *(__nv_bfloat162*)(Clo + (size_t)grow0 * HH + col) = l0b;
        *(__nv_bfloat162*)(Chi + (size_t)grow1 * HH + col) = h1;
        *(__nv_bfloat162*)(Clo + (size_t)grow1 * HH + col) = l1b;
    }
}

// ---------------------------------------------------------------------------
// Launch
// ---------------------------------------------------------------------------
extern "C" void kernel_launch(void* const* d_in, const int* in_sizes, int n_in,
                              void* d_out, int out_size)
{
    const float* input = (const float*)d_in[0];
    const float* mask  = (const float*)d_in[1];
    const float* nw    = (const float*)d_in[2];
    const float* nb    = (const float*)d_in[3];
    const float* qkvw  = (const float*)d_in[4];
    const float* qkvb  = (const float*)d_in[5];
    const float* ow    = (const float*)d_in[6];

    float* out     = (float*)d_out;
    float* key_out = out + (size_t)TENSOR_ELEMS;
    float* val_out = out + (size_t)2 * TENSOR_ELEMS;
    float* ctx_out = out + (size_t)3 * TENSOR_ELEMS;

    __nv_bfloat16 *a_hi, *a_lo, *w_hi, *w_lo, *ow_hi, *ow_lo;
    __nv_bfloat16 *q_hi, *q_lo, *k_hi, *k_lo, *v_hi, *v_lo, *c_hi, *c_lo;
    cudaGetSymbolAddress((void**)&a_hi, g_a_hi);
    cudaGetSymbolAddress((void**)&a_lo, g_a_lo);
    cudaGetSymbolAddress((void**)&w_hi, g_w_hi);
    cudaGetSymbolAddress((void**)&w_lo, g_w_lo);
    cudaGetSymbolAddress((void**)&ow_hi, g_ow_hi);
    cudaGetSymbolAddress((void**)&ow_lo, g_ow_lo);
    cudaGetSymbolAddress((void**)&q_hi, g_q_hi);
    cudaGetSymbolAddress((void**)&q_lo, g_q_lo);
    cudaGetSymbolAddress((void**)&k_hi, g_k_hi);
    cudaGetSymbolAddress((void**)&k_lo, g_k_lo);
    cudaGetSymbolAddress((void**)&v_hi, g_v_hi);
    cudaGetSymbolAddress((void**)&v_lo, g_v_lo);
    cudaGetSymbolAddress((void**)&c_hi, g_c_hi);
    cudaGetSymbolAddress((void**)&c_lo, g_c_lo);

    // 1) LayerNorm -> bf16 split
    ln_kernel<<<MROWS, 256>>>(input, nw, nb, a_hi, a_lo);

    // 2) Weight splits
    split_kernel<<<(3 * HH * HH / 4 + 255) / 256, 256>>>(qkvw, w_hi, w_lo, 3 * HH * HH / 4);
    split_kernel<<<(HH * HH / 4 + 255) / 256, 256>>>(ow, ow_hi, ow_lo, HH * HH / 4);

    // 3) QKV GEMM: fp32 K/V outputs + bf16 hi/lo Q/K/V scratch
    {
        dim3 grid(3072 / 128, MROWS / 128);
        gemm_mma<true><<<grid, 256>>>(a_hi, a_lo, w_hi, w_lo, qkvb,
                                      key_out, val_out, nullptr,
                                      q_hi, q_lo, k_hi, k_lo, v_hi, v_lo,
                                      HH, 3 * HH);
    }

    // 4) Flash attention (HMMA) -> ctx fp32 + ctx bf16 hi/lo
    {
        dim3 grid(SS / 64, NHEADS, BB);
        attn_mma<<<grid, 128>>>(q_hi, q_lo, k_hi, k_lo, v_hi, v_lo,
                                mask, ctx_out, c_hi, c_lo);
    }

    // 5) Output projection
    {
        dim3 grid(HH / 128, MROWS / 128);
        gemm_mma<false><<<grid, 256>>>(c_hi, c_lo, ow_hi, ow_lo, nullptr,
                                       nullptr, nullptr, out,
                                       nullptr, nullptr, nullptr, nullptr, nullptr, nullptr,
                                       HH, HH);
    }
}

// round 12
// speedup vs baseline: 3.2734x; 1.1756x over previous
#include <cuda_runtime.h>
#include <cuda_bf16.h>
#include <math.h>
#include <stdint.h>

// Problem constants (fixed by the reference)
#define BB 4
#define SS 2048
#define HH 1024
#define NHEADS 16
#define DHEAD 64
#define MROWS (BB * SS)            // 8192
#define TENSOR_ELEMS (MROWS * HH)  // 8,388,608 per output tensor

// ---------------------------------------------------------------------------
// Scratch (__device__ globals; no runtime allocation allowed)
// ---------------------------------------------------------------------------
__device__ __nv_bfloat16 g_a_hi[MROWS * HH];
__device__ __nv_bfloat16 g_a_lo[MROWS * HH];
__device__ __nv_bfloat16 g_w_hi[3 * HH * HH];
__device__ __nv_bfloat16 g_w_lo[3 * HH * HH];
__device__ __nv_bfloat16 g_ow_hi[HH * HH];
__device__ __nv_bfloat16 g_ow_lo[HH * HH];
__device__ __nv_bfloat16 g_q_hi[MROWS * HH];
__device__ __nv_bfloat16 g_q_lo[MROWS * HH];
__device__ __nv_bfloat16 g_k_hi[MROWS * HH];
__device__ __nv_bfloat16 g_k_lo[MROWS * HH];
__device__ __nv_bfloat16 g_v_hi[MROWS * HH];
__device__ __nv_bfloat16 g_v_lo[MROWS * HH];
__device__ __nv_bfloat16 g_c_hi[MROWS * HH];
__device__ __nv_bfloat16 g_c_lo[MROWS * HH];

// ---------------------------------------------------------------------------
// PTX helpers — target-portable (sm_80+)
// ---------------------------------------------------------------------------
__device__ __forceinline__ uint32_t smem_u32(const void* p) {
    uint32_t a;
    asm("{ .reg .u64 t; cvta.to.shared.u64 t, %1; cvt.u32.u64 %0, t; }" : "=r"(a) : "l"(p));
    return a;
}
#define CP_ASYNC16(dst, src) \
    asm volatile("cp.async.cg.shared.global [%0], [%1], 16;" :: "r"(dst), "l"(src))
#define CP_COMMIT() asm volatile("cp.async.commit_group;" ::: "memory")
#define CP_WAIT0()  asm volatile("cp.async.wait_group 0;" ::: "memory")
#define CP_WAIT1()  asm volatile("cp.async.wait_group 1;" ::: "memory")

__device__ __forceinline__ void ldm_x4(uint32_t* r, uint32_t addr) {
    asm volatile("ldmatrix.sync.aligned.m8n8.x4.shared.b16 {%0,%1,%2,%3}, [%4];"
                 : "=r"(r[0]), "=r"(r[1]), "=r"(r[2]), "=r"(r[3]) : "r"(addr));
}
__device__ __forceinline__ void ldm_x4t(uint32_t* r, uint32_t addr) {
    asm volatile("ldmatrix.sync.aligned.m8n8.x4.trans.shared.b16 {%0,%1,%2,%3}, [%4];"
                 : "=r"(r[0]), "=r"(r[1]), "=r"(r[2]), "=r"(r[3]) : "r"(addr));
}
__device__ __forceinline__ void mma16816(float* c, const uint32_t* a, const uint32_t* b) {
    asm volatile(
        "mma.sync.aligned.m16n8k16.row.col.f32.bf16.bf16.f32 "
        "{%0,%1,%2,%3}, {%4,%5,%6,%7}, {%8,%9}, {%0,%1,%2,%3};"
        : "+f"(c[0]), "+f"(c[1]), "+f"(c[2]), "+f"(c[3])
        : "r"(a[0]), "r"(a[1]), "r"(a[2]), "r"(a[3]), "r"(b[0]), "r"(b[1]));
}

// ---------------------------------------------------------------------------
// Kernel 1: LayerNorm -> bf16 hi/lo split. One block per row, 256 threads.
// ---------------------------------------------------------------------------
__global__ __launch_bounds__(256)
void ln_kernel(const float* __restrict__ x,
               const float* __restrict__ w,
               const float* __restrict__ bvec,
               __nv_bfloat16* __restrict__ yhi,
               __nv_bfloat16* __restrict__ ylo)
{
    const int row = blockIdx.x;
    const int t = threadIdx.x;
    const float4 xv = ((const float4*)(x + (size_t)row * HH))[t];

    float s  = xv.x + xv.y + xv.z + xv.w;
    float ss = xv.x * xv.x + xv.y * xv.y + xv.z * xv.z + xv.w * xv.w;
    #pragma unroll
    for (int o = 16; o > 0; o >>= 1) {
        s  += __shfl_xor_sync(0xFFFFFFFFu, s,  o);
        ss += __shfl_xor_sync(0xFFFFFFFFu, ss, o);
    }
    __shared__ float rs[8], rss[8];
    __shared__ float smu, srstd;
    const int wid = t >> 5, lane = t & 31;
    if (lane == 0) { rs[wid] = s; rss[wid] = ss; }
    __syncthreads();
    if (t == 0) {
        float a = 0.f, b2 = 0.f;
        #pragma unroll
        for (int i = 0; i < 8; i++) { a += rs[i]; b2 += rss[i]; }
        const float mu = a * (1.0f / HH);
        float var = b2 * (1.0f / HH) - mu * mu;
        smu = mu;
        srstd = rsqrtf(var + 1e-12f);
    }
    __syncthreads();
    const float mu = smu, rstd = srstd;
    const float4 wv = ((const float4*)w)[t];
    const float4 bv = ((const float4*)bvec)[t];
    float v[4];
    v[0] = (xv.x - mu) * rstd * wv.x + bv.x;
    v[1] = (xv.y - mu) * rstd * wv.y + bv.y;
    v[2] = (xv.z - mu) * rstd * wv.z + bv.z;
    v[3] = (xv.w - mu) * rstd * wv.w + bv.w;
    __nv_bfloat16 hi[4], lo[4];
    #pragma unroll
    for (int i = 0; i < 4; i++) {
        hi[i] = __float2bfloat16_rn(v[i]);
        lo[i] = __float2bfloat16_rn(v[i] - __bfloat162float(hi[i]));
    }
    const size_t base = (size_t)row * HH + t * 4;
    *(uint64_t*)(yhi + base) = *(uint64_t*)hi;
    *(uint64_t*)(ylo + base) = *(uint64_t*)lo;
}

// ---------------------------------------------------------------------------
// Kernel: fp32 -> bf16 hi/lo split (weights)
// ---------------------------------------------------------------------------
__global__ __launch_bounds__(256)
void split_kernel(const float* __restrict__ x,
                  __nv_bfloat16* __restrict__ hi,
                  __nv_bfloat16* __restrict__ lo, int n4)
{
    const int i = blockIdx.x * 256 + threadIdx.x;
    if (i >= n4) return;
    const float4 v = ((const float4*)x)[i];
    __nv_bfloat16 h[4], l[4];
    const float vv[4] = {v.x, v.y, v.z, v.w};
    #pragma unroll
    for (int j = 0; j < 4; j++) {
        h[j] = __float2bfloat16_rn(vv[j]);
        l[j] = __float2bfloat16_rn(vv[j] - __bfloat162float(h[j]));
    }
    ((uint64_t*)hi)[i] = *(uint64_t*)h;
    ((uint64_t*)lo)[i] = *(uint64_t*)l;
}

// ---------------------------------------------------------------------------
// bf16 3-pass split GEMM (HMMA), 3-stage cp.async ring, x4 B-fragment loads.
// Dynamic smem: 3 stages x (As 128x40 + Bs 128x40) bf16 = 61440 B.
// ---------------------------------------------------------------------------
template<bool SPLIT>
__global__ __launch_bounds__(256)
void gemm_mma(const __nv_bfloat16* __restrict__ Ahi, const __nv_bfloat16* __restrict__ Alo,
              const __nv_bfloat16* __restrict__ Bhi, const __nv_bfloat16* __restrict__ Blo,
              const float* __restrict__ bias,
              float* __restrict__ F1, float* __restrict__ F2,
              float* __restrict__ C0,
              __nv_bfloat16* __restrict__ H0, __nv_bfloat16* __restrict__ L0,
              __nv_bfloat16* __restrict__ H1, __nv_bfloat16* __restrict__ L1,
              __nv_bfloat16* __restrict__ H2, __nv_bfloat16* __restrict__ L2,
              int K, int N)
{
    constexpr int BK = 32, STR = 40;
    constexpr int STAGE = 2 * 128 * STR * 2;   // bytes per stage (A+B)
    extern __shared__ char dsm[];
    const uint32_t sb = smem_u32(dsm);

    const int t = threadIdx.x;
    const int wid = t >> 5, lane = t & 31;
    const int warp_m = wid >> 2;
    const int warp_n = wid & 3;
    const int bm = blockIdx.y * 128;
    const int bn = blockIdx.x * 128;

    float acc[4][4][4];
    #pragma unroll
    for (int i = 0; i < 4; i++)
        #pragma unroll
        for (int j = 0; j < 4; j++)
            #pragma unroll
            for (int r = 0; r < 4; r++) acc[i][j][r] = 0.f;

    const int nkp = K / BK;
    const int nk = 3 * nkp;

    const int r0 = t >> 2, ch = (t & 3) * 8;
    const uint32_t soff0 = (uint32_t)(r0 * STR + ch) * 2;
    const uint32_t soff1 = (uint32_t)((r0 + 64) * STR + ch) * 2;

    auto issue = [&](int i) {
        const int s = i % 3;
        const uint32_t sA = sb + s * STAGE;
        const uint32_t sB = sA + 128 * STR * 2;
        const int p = i / nkp;
        const int k0 = (i - p * nkp) * BK;
        const __nv_bfloat16* Ap = (p == 2) ? Alo : Ahi;
        const __nv_bfloat16* Bp = (p == 1) ? Blo : Bhi;
        CP_ASYNC16(sA + soff0, Ap + (size_t)(bm + r0) * K + k0 + ch);
        CP_ASYNC16(sA + soff1, Ap + (size_t)(bm + r0 + 64) * K + k0 + ch);
        CP_ASYNC16(sB + soff0, Bp + (size_t)(bn + r0) * K + k0 + ch);
        CP_ASYNC16(sB + soff1, Bp + (size_t)(bn + r0 + 64) * K + k0 + ch);
        CP_COMMIT();
    };

    issue(0);
    issue(1);
    for (int i = 0; i < nk; i++) {
        if (i < nk - 1) { CP_WAIT1(); } else { CP_WAIT0(); }
        __syncthreads();
        if (i + 2 < nk) issue(i + 2);
        const int s = i % 3;
        const uint32_t sA = sb + s * STAGE;
        const uint32_t sB = sA + 128 * STR * 2;

        #pragma unroll
        for (int ks = 0; ks < 2; ks++) {
            uint32_t a[4][4];
            uint32_t b[2][4];   // b[nt2] holds fragments for n-tiles 2*nt2, 2*nt2+1
            #pragma unroll
            for (int mt = 0; mt < 4; mt++) {
                const int row = warp_m * 64 + mt * 16 + (lane & 15);
                const int kc = ks * 16 + ((lane >> 4) * 8);
                ldm_x4(a[mt], sA + (uint32_t)(row * STR + kc) * 2);
            }
            #pragma unroll
            for (int nt2 = 0; nt2 < 2; nt2++) {
                const int row = warp_n * 32 + nt2 * 16 + ((lane >> 4) * 8) + (lane & 7);
                const int kc = ks * 16 + (((lane >> 3) & 1) * 8);
                ldm_x4(b[nt2], sB + (uint32_t)(row * STR + kc) * 2);
            }
            #pragma unroll
            for (int mt = 0; mt < 4; mt++)
                #pragma unroll
                for (int nt = 0; nt < 4; nt++)
                    mma16816(acc[mt][nt], a[mt], &b[nt >> 1][(nt & 1) * 2]);
        }
    }

    // Epilogue
    const int sec = bn >> 10;
    float* Fsec = nullptr;
    __nv_bfloat16 *Hsec = nullptr, *Lsec = nullptr;
    int cstride = N;
    if (SPLIT) {
        Fsec = (sec == 0) ? nullptr : ((sec == 1) ? F1 : F2);
        Hsec = (sec == 0) ? H0 : ((sec == 1) ? H1 : H2);
        Lsec = (sec == 0) ? L0 : ((sec == 1) ? L1 : L2);
        cstride = 1024;
    }

    #pragma unroll
    for (int mt = 0; mt < 4; mt++) {
        const int m0 = bm + warp_m * 64 + mt * 16 + (lane >> 2);
        #pragma unroll
        for (int nt = 0; nt < 4; nt++) {
            const int n0 = bn + warp_n * 32 + nt * 8 + (lane & 3) * 2;
            float b0 = 0.f, b1 = 0.f;
            if (bias) { b0 = bias[n0]; b1 = bias[n0 + 1]; }
            const int col = SPLIT ? (n0 & 1023) : n0;
            float2 v0 = { acc[mt][nt][0] + b0, acc[mt][nt][1] + b1 };
            float2 v1 = { acc[mt][nt][2] + b0, acc[mt][nt][3] + b1 };
            if (SPLIT) {
                if (Fsec) {
                    *(float2*)(Fsec + (size_t)m0 * cstride + col)       = v0;
                    *(float2*)(Fsec + (size_t)(m0 + 8) * cstride + col) = v1;
                }
                __nv_bfloat162 h0 = __float22bfloat162_rn(v0);
                __nv_bfloat162 l0;
                l0.x = __float2bfloat16_rn(v0.x - __bfloat162float(h0.x));
                l0.y = __float2bfloat16_rn(v0.y - __bfloat162float(h0.y));
                __nv_bfloat162 h1 = __float22bfloat162_rn(v1);
                __nv_bfloat162 l1;
                l1.x = __float2bfloat16_rn(v1.x - __bfloat162float(h1.x));
                l1.y = __float2bfloat16_rn(v1.y - __bfloat162float(h1.y));
                *(__nv_bfloat162*)(Hsec + (size_t)m0 * 1024 + col)       = h0;
                *(__nv_bfloat162*)(Lsec + (size_t)m0 * 1024 + col)       = l0;
                *(__nv_bfloat162*)(Hsec + (size_t)(m0 + 8) * 1024 + col) = h1;
                *(__nv_bfloat162*)(Lsec + (size_t)(m0 + 8) * 1024 + col) = l1;
            } else {
                *(float2*)(C0 + (size_t)m0 * cstride + col)       = v0;
                *(float2*)(C0 + (size_t)(m0 + 8) * cstride + col) = v1;
            }
        }
    }
}

// ---------------------------------------------------------------------------
// Flash attention on HMMA, 2-stage cp.async K/V ring, x4 fragment loads.
// CTA: 64 q-rows, 4 warps. Dynamic smem: 2 x (4 tiles 64x72 bf16 + mask) = 74240 B.
// ---------------------------------------------------------------------------
__global__ __launch_bounds__(128)
void attn_mma(const __nv_bfloat16* __restrict__ Qh, const __nv_bfloat16* __restrict__ Ql,
              const __nv_bfloat16* __restrict__ Kh, const __nv_bfloat16* __restrict__ Kl,
              const __nv_bfloat16* __restrict__ Vh, const __nv_bfloat16* __restrict__ Vl,
              const float* __restrict__ mask, float* __restrict__ Ctx,
              __nv_bfloat16* __restrict__ Chi, __nv_bfloat16* __restrict__ Clo)
{
    constexpr int STR = 72;
    constexpr int TILE = 64 * STR * 2;          // 9216 B
    constexpr int STAGE = 4 * TILE + 256;       // + mask, 37120 B
    extern __shared__ char dsm[];
    const uint32_t sb = smem_u32(dsm);

    const int b = blockIdx.z, h = blockIdx.y, qt = blockIdx.x;
    const int t = threadIdx.x, wid = t >> 5, lane = t & 31;
    const float scale = 0.125f;
    const int nkt = SS / 64;

    // ---- stage Q tile (64x64 hi/lo) into stage-0 region and load fragments
    {
        const size_t qbase = (size_t)(b * SS + qt * 64) * HH + h * DHEAD;
        #pragma unroll
        for (int i = 0; i < 4; i++) {
            const int id = t + i * 128;
            const int r = id >> 3, c = (id & 7) * 8;
            *(uint4*)(dsm + (r * STR + c) * 2)        = *(const uint4*)(Qh + qbase + (size_t)r * HH + c);
            *(uint4*)(dsm + TILE + (r * STR + c) * 2) = *(const uint4*)(Ql + qbase + (size_t)r * HH + c);
        }
    }
    __syncthreads();
    uint32_t qhf[4][4], qlf[4][4];
    {
        const int row = wid * 16 + (lane & 15);
        #pragma unroll
        for (int ks = 0; ks < 4; ks++) {
            const int kc = ks * 16 + ((lane >> 4) * 8);
            ldm_x4(qhf[ks], sb + (uint32_t)(row * STR + kc) * 2);
            ldm_x4(qlf[ks], sb + TILE + (uint32_t)(row * STR + kc) * 2);
        }
    }
    __syncthreads();

    // ---- cp.async issue of K/V/mask for tile kt into stage kt&1
    auto issue = [&](int kt) {
        const int s = kt & 1;
        const uint32_t st = sb + s * STAGE;
        const size_t kbase = (size_t)(b * SS + kt * 64) * HH + h * DHEAD;
        const __nv_bfloat16* tp0 = Kh; const __nv_bfloat16* tp1 = Kl;
        const __nv_bfloat16* tp2 = Vh; const __nv_bfloat16* tp3 = Vl;
        #pragma unroll
        for (int i = 0; i < 16; i++) {
            const int id = t + i * 128;
            const int tile = id >> 9;
            const int r = (id >> 3) & 63, c = (id & 7) * 8;
            const __nv_bfloat16* tp = (tile == 0) ? tp0 : ((tile == 1) ? tp1 : ((tile == 2) ? tp2 : tp3));
            CP_ASYNC16(st + tile * TILE + (uint32_t)(r * STR + c) * 2,
                       tp + kbase + (size_t)r * HH + c);
        }
        if (t < 16) CP_ASYNC16(st + 4 * TILE + t * 16, mask + b * SS + kt * 64 + t * 4);
        CP_COMMIT();
    };

    // ---- flash state
    float o[8][4];
    #pragma unroll
    for (int nt = 0; nt < 8; nt++)
        #pragma unroll
        for (int r = 0; r < 4; r++) o[nt][r] = 0.f;
    float m0 = -INFINITY, m1 = -INFINITY;
    float l0 = 0.f, l1 = 0.f;

    issue(0);
    for (int kt = 0; kt < nkt; kt++) {
        if (kt + 1 < nkt) issue(kt + 1);
        if (kt + 1 < nkt) { CP_WAIT1(); } else { CP_WAIT0(); }
        __syncthreads();

        const int s = kt & 1;
        const uint32_t sKh = sb + s * STAGE;
        const uint32_t sKl = sKh + TILE;
        const uint32_t sVh = sKh + 2 * TILE;
        const uint32_t sVl = sKh + 3 * TILE;
        const float* mskp = (const float*)(dsm + s * STAGE + 4 * TILE);

        // ---- S = Qh@Kh^T + Qh@Kl^T + Ql@Kh^T  (16 x 64 per warp)
        float sacc[8][4];
        #pragma unroll
        for (int nt = 0; nt < 8; nt++)
            #pragma unroll
            for (int r = 0; r < 4; r++) sacc[nt][r] = 0.f;

        #pragma unroll
        for (int ks = 0; ks < 4; ks++) {
            #pragma unroll
            for (int nt2 = 0; nt2 < 4; nt2++) {
                uint32_t bh[4], bl[4];
                const int row = nt2 * 16 + ((lane >> 4) * 8) + (lane & 7);
                const int kc = ks * 16 + (((lane >> 3) & 1) * 8);
                const uint32_t off = (uint32_t)(row * STR + kc) * 2;
                ldm_x4(bh, sKh + off);
                ldm_x4(bl, sKl + off);
                mma16816(sacc[2 * nt2],     qhf[ks], &bh[0]);
                mma16816(sacc[2 * nt2],     qhf[ks], &bl[0]);
                mma16816(sacc[2 * nt2],     qlf[ks], &bh[0]);
                mma16816(sacc[2 * nt2 + 1], qhf[ks], &bh[2]);
                mma16816(sacc[2 * nt2 + 1], qhf[ks], &bl[2]);
                mma16816(sacc[2 * nt2 + 1], qlf[ks], &bh[2]);
            }
        }

        // ---- softmax (rows r=lane/4 and r+8; cols per nt: nt*8+(lane&3)*2,+1)
        float nm0 = m0, nm1 = m1;
        #pragma unroll
        for (int nt = 0; nt < 8; nt++) {
            const int c0 = nt * 8 + (lane & 3) * 2;
            const float mk0 = mskp[c0], mk1 = mskp[c0 + 1];
            sacc[nt][0] = sacc[nt][0] * scale + mk0;
            sacc[nt][1] = sacc[nt][1] * scale + mk1;
            sacc[nt][2] = sacc[nt][2] * scale + mk0;
            sacc[nt][3] = sacc[nt][3] * scale + mk1;
            nm0 = fmaxf(nm0, fmaxf(sacc[nt][0], sacc[nt][1]));
            nm1 = fmaxf(nm1, fmaxf(sacc[nt][2], sacc[nt][3]));
        }
        nm0 = fmaxf(nm0, __shfl_xor_sync(0xFFFFFFFFu, nm0, 1));
        nm0 = fmaxf(nm0, __shfl_xor_sync(0xFFFFFFFFu, nm0, 2));
        nm1 = fmaxf(nm1, __shfl_xor_sync(0xFFFFFFFFu, nm1, 1));
        nm1 = fmaxf(nm1, __shfl_xor_sync(0xFFFFFFFFu, nm1, 2));

        const float cr0 = __expf(m0 - nm0);
        const float cr1 = __expf(m1 - nm1);
        l0 *= cr0; l1 *= cr1;
        #pragma unroll
        for (int nt = 0; nt < 8; nt++) {
            o[nt][0] *= cr0; o[nt][1] *= cr0;
            o[nt][2] *= cr1; o[nt][3] *= cr1;
        }
        #pragma unroll
        for (int nt = 0; nt < 8; nt++) {
            sacc[nt][0] = __expf(sacc[nt][0] - nm0);
            sacc[nt][1] = __expf(sacc[nt][1] - nm0);
            sacc[nt][2] = __expf(sacc[nt][2] - nm1);
            sacc[nt][3] = __expf(sacc[nt][3] - nm1);
            l0 += sacc[nt][0] + sacc[nt][1];
            l1 += sacc[nt][2] + sacc[nt][3];
        }
        m0 = nm0; m1 = nm1;

        // ---- PV: per k-step ks, P A-frag from S n-tiles (2ks, 2ks+1)
        #pragma unroll
        for (int ks = 0; ks < 4; ks++) {
            uint32_t ph[4], pl[4];
            {
                const float* sa = sacc[2 * ks];
                const float* sbp = sacc[2 * ks + 1];
                __nv_bfloat162 hh, ll;
                float2 f;
                f.x = sa[0]; f.y = sa[1];
                hh = __float22bfloat162_rn(f);
                ll.x = __float2bfloat16_rn(f.x - __bfloat162float(hh.x));
                ll.y = __float2bfloat16_rn(f.y - __bfloat162float(hh.y));
                ph[0] = *(uint32_t*)&hh; pl[0] = *(uint32_t*)&ll;
                f.x = sa[2]; f.y = sa[3];
                hh = __float22bfloat162_rn(f);
                ll.x = __float2bfloat16_rn(f.x - __bfloat162float(hh.x));
                ll.y = __float2bfloat16_rn(f.y - __bfloat162float(hh.y));
                ph[1] = *(uint32_t*)&hh; pl[1] = *(uint32_t*)&ll;
                f.x = sbp[0]; f.y = sbp[1];
                hh = __float22bfloat162_rn(f);
                ll.x = __float2bfloat16_rn(f.x - __bfloat162float(hh.x));
                ll.y = __float2bfloat16_rn(f.y - __bfloat162float(hh.y));
                ph[2] = *(uint32_t*)&hh; pl[2] = *(uint32_t*)&ll;
                f.x = sbp[2]; f.y = sbp[3];
                hh = __float22bfloat162_rn(f);
                ll.x = __float2bfloat16_rn(f.x - __bfloat162float(hh.x));
                ll.y = __float2bfloat16_rn(f.y - __bfloat162float(hh.y));
                ph[3] = *(uint32_t*)&hh; pl[3] = *(uint32_t*)&ll;
            }
            #pragma unroll
            for (int nt2 = 0; nt2 < 4; nt2++) {
                uint32_t vh[4], vl[4];
                const int row = ks * 16 + (((lane >> 3) & 1) * 8) + (lane & 7);
                const int col = nt2 * 16 + ((lane >> 4) * 8);
                const uint32_t off = (uint32_t)(row * STR + col) * 2;
                ldm_x4t(vh, sVh + off);
                ldm_x4t(vl, sVl + off);
                mma16816(o[2 * nt2],     ph, &vh[0]);
                mma16816(o[2 * nt2],     ph, &vl[0]);
                mma16816(o[2 * nt2],     pl, &vh[0]);
                mma16816(o[2 * nt2 + 1], ph, &vh[2]);
                mma16816(o[2 * nt2 + 1], ph, &vl[2]);
                mma16816(o[2 * nt2 + 1], pl, &vh[2]);
            }
        }
        __syncthreads();
    }

    // ---- final reduce + write
    l0 += __shfl_xor_sync(0xFFFFFFFFu, l0, 1);
    l0 += __shfl_xor_sync(0xFFFFFFFFu, l0, 2);
    l1 += __shfl_xor_sync(0xFFFFFFFFu, l1, 1);
    l1 += __shfl_xor_sync(0xFFFFFFFFu, l1, 2);
    const float inv0 = 1.0f / l0;
    const float inv1 = 1.0f / l1;

    const int grow0 = b * SS + qt * 64 + wid * 16 + (lane >> 2);
    const int grow1 = grow0 + 8;
    #pragma unroll
    for (int nt = 0; nt < 8; nt++) {
        const int col = h * DHEAD + nt * 8 + (lane & 3) * 2;
        float2 v0 = { o[nt][0] * inv0, o[nt][1] * inv0 };
        float2 v1 = { o[nt][2] * inv1, o[nt][3] * inv1 };
        *(float2*)(Ctx + (size_t)grow0 * HH + col) = v0;
        *(float2*)(Ctx + (size_t)grow1 * HH + col) = v1;
        __nv_bfloat162 h0 = __float22bfloat162_rn(v0);
        __nv_bfloat162 l0b;
        l0b.x = __float2bfloat16_rn(v0.x - __bfloat162float(h0.x));
        l0b.y = __float2bfloat16_rn(v0.y - __bfloat162float(h0.y));
        __nv_bfloat162 h1 = __float22bfloat162_rn(v1);
        __nv_bfloat162 l1b;
        l1b.x = __float2bfloat16_rn(v1.x - __bfloat162float(h1.x));
        l1b.y = __float2bfloat16_rn(v1.y - __bfloat162float(h1.y));
        *(__nv_bfloat162*)(Chi + (size_t)grow0 * HH + col) = h0;
        *(__nv_bfloat162*)(Clo + (size_t)grow0 * HH + col) = l0b;
        *(__nv_bfloat162*)(Chi + (size_t)grow1 * HH + col) = h1;
        *(__nv_bfloat162*)(Clo + (size_t)grow1 * HH + col) = l1b;
    }
}

// ---------------------------------------------------------------------------
// Launch
// ---------------------------------------------------------------------------
extern "C" void kernel_launch(void* const* d_in, const int* in_sizes, int n_in,
                              void* d_out, int out_size)
{
    const float* input = (const float*)d_in[0];
    const float* mask  = (const float*)d_in[1];
    const float* nw    = (const float*)d_in[2];
    const float* nb    = (const float*)d_in[3];
    const float* qkvw  = (const float*)d_in[4];
    const float* qkvb  = (const float*)d_in[5];
    const float* ow    = (const float*)d_in[6];

    float* out     = (float*)d_out;
    float* key_out = out + (size_t)TENSOR_ELEMS;
    float* val_out = out + (size_t)2 * TENSOR_ELEMS;
    float* ctx_out = out + (size_t)3 * TENSOR_ELEMS;

    __nv_bfloat16 *a_hi, *a_lo, *w_hi, *w_lo, *ow_hi, *ow_lo;
    __nv_bfloat16 *q_hi, *q_lo, *k_hi, *k_lo, *v_hi, *v_lo, *c_hi, *c_lo;
    cudaGetSymbolAddress((void**)&a_hi, g_a_hi);
    cudaGetSymbolAddress((void**)&a_lo, g_a_lo);
    cudaGetSymbolAddress((void**)&w_hi, g_w_hi);
    cudaGetSymbolAddress((void**)&w_lo, g_w_lo);
    cudaGetSymbolAddress((void**)&ow_hi, g_ow_hi);
    cudaGetSymbolAddress((void**)&ow_lo, g_ow_lo);
    cudaGetSymbolAddress((void**)&q_hi, g_q_hi);
    cudaGetSymbolAddress((void**)&q_lo, g_q_lo);
    cudaGetSymbolAddress((void**)&k_hi, g_k_hi);
    cudaGetSymbolAddress((void**)&k_lo, g_k_lo);
    cudaGetSymbolAddress((void**)&v_hi, g_v_hi);
    cudaGetSymbolAddress((void**)&v_lo, g_v_lo);
    cudaGetSymbolAddress((void**)&c_hi, g_c_hi);
    cudaGetSymbolAddress((void**)&c_lo, g_c_lo);

    const int GEMM_DYN = 3 * 2 * 128 * 40 * 2;     // 61440
    const int ATTN_DYN = 2 * (4 * 64 * 72 * 2 + 256);  // 74240
    cudaFuncSetAttribute(gemm_mma<true>,  cudaFuncAttributeMaxDynamicSharedMemorySize, GEMM_DYN);
    cudaFuncSetAttribute(gemm_mma<false>, cudaFuncAttributeMaxDynamicSharedMemorySize, GEMM_DYN);
    cudaFuncSetAttribute(attn_mma, cudaFuncAttributeMaxDynamicSharedMemorySize, ATTN_DYN);

    // 1) LayerNorm -> bf16 split
    ln_kernel<<<MROWS, 256>>>(input, nw, nb, a_hi, a_lo);

    // 2) Weight splits
    split_kernel<<<(3 * HH * HH / 4 + 255) / 256, 256>>>(qkvw, w_hi, w_lo, 3 * HH * HH / 4);
    split_kernel<<<(HH * HH / 4 + 255) / 256, 256>>>(ow, ow_hi, ow_lo, HH * HH / 4);

    // 3) QKV GEMM: fp32 K/V outputs + bf16 hi/lo Q/K/V scratch
    {
        dim3 grid(3072 / 128, MROWS / 128);
        gemm_mma<true><<<grid, 256, GEMM_DYN>>>(a_hi, a_lo, w_hi, w_lo, qkvb,
                                                key_out, val_out, nullptr,
                                                q_hi, q_lo, k_hi, k_lo, v_hi, v_lo,
                                                HH, 3 * HH);
    }

    // 4) Flash attention (HMMA) -> ctx fp32 + ctx bf16 hi/lo
    {
        dim3 grid(SS / 64, NHEADS, BB);
        attn_mma<<<grid, 128, ATTN_DYN>>>(q_hi, q_lo, k_hi, k_lo, v_hi, v_lo,
                                          mask, ctx_out, c_hi, c_lo);
    }

    // 5) Output projection
    {
        dim3 grid(HH / 128, MROWS / 128);
        gemm_mma<false><<<grid, 256, GEMM_DYN>>>(c_hi, c_lo, ow_hi, ow_lo, nullptr,
                                                 nullptr, nullptr, out,
                                                 nullptr, nullptr, nullptr, nullptr, nullptr, nullptr,
                                                 HH, HH);
    }
}

// round 13
// speedup vs baseline: 3.5835x; 1.0947x over previous
#include <cuda_runtime.h>
#include <cuda_bf16.h>
#include <math.h>
#include <stdint.h>

// Problem constants (fixed by the reference)
#define BB 4
#define SS 2048
#define HH 1024
#define NHEADS 16
#define DHEAD 64
#define MROWS (BB * SS)            // 8192
#define TENSOR_ELEMS (MROWS * HH)  // 8,388,608 per output tensor

// ---------------------------------------------------------------------------
// Scratch (__device__ globals; no runtime allocation allowed)
// ---------------------------------------------------------------------------
__device__ __nv_bfloat16 g_a_hi[MROWS * HH];
__device__ __nv_bfloat16 g_a_lo[MROWS * HH];
__device__ __nv_bfloat16 g_w_hi[3 * HH * HH];
__device__ __nv_bfloat16 g_w_lo[3 * HH * HH];
__device__ __nv_bfloat16 g_ow_hi[HH * HH];
__device__ __nv_bfloat16 g_ow_lo[HH * HH];
__device__ __nv_bfloat16 g_q_hi[MROWS * HH];
__device__ __nv_bfloat16 g_q_lo[MROWS * HH];
__device__ __nv_bfloat16 g_k_hi[MROWS * HH];
__device__ __nv_bfloat16 g_k_lo[MROWS * HH];
__device__ __nv_bfloat16 g_v_hi[MROWS * HH];
__device__ __nv_bfloat16 g_v_lo[MROWS * HH];
__device__ __nv_bfloat16 g_c_hi[MROWS * HH];
__device__ __nv_bfloat16 g_c_lo[MROWS * HH];

// ---------------------------------------------------------------------------
// PTX helpers — target-portable (sm_80+)
// ---------------------------------------------------------------------------
__device__ __forceinline__ uint32_t smem_u32(const void* p) {
    uint32_t a;
    asm("{ .reg .u64 t; cvta.to.shared.u64 t, %1; cvt.u32.u64 %0, t; }" : "=r"(a) : "l"(p));
    return a;
}
#define CP_ASYNC16(dst, src) \
    asm volatile("cp.async.cg.shared.global [%0], [%1], 16;" :: "r"(dst), "l"(src))
#define CP_COMMIT() asm volatile("cp.async.commit_group;" ::: "memory")
#define CP_WAIT0()  asm volatile("cp.async.wait_group 0;" ::: "memory")
#define CP_WAIT1()  asm volatile("cp.async.wait_group 1;" ::: "memory")

__device__ __forceinline__ void ldm_x4(uint32_t* r, uint32_t addr) {
    asm volatile("ldmatrix.sync.aligned.m8n8.x4.shared.b16 {%0,%1,%2,%3}, [%4];"
                 : "=r"(r[0]), "=r"(r[1]), "=r"(r[2]), "=r"(r[3]) : "r"(addr));
}
__device__ __forceinline__ void ldm_x4t(uint32_t* r, uint32_t addr) {
    asm volatile("ldmatrix.sync.aligned.m8n8.x4.trans.shared.b16 {%0,%1,%2,%3}, [%4];"
                 : "=r"(r[0]), "=r"(r[1]), "=r"(r[2]), "=r"(r[3]) : "r"(addr));
}
__device__ __forceinline__ void mma16816(float* c, const uint32_t* a, const uint32_t* b) {
    asm volatile(
        "mma.sync.aligned.m16n8k16.row.col.f32.bf16.bf16.f32 "
        "{%0,%1,%2,%3}, {%4,%5,%6,%7}, {%8,%9}, {%0,%1,%2,%3};"
        : "+f"(c[0]), "+f"(c[1]), "+f"(c[2]), "+f"(c[3])
        : "r"(a[0]), "r"(a[1]), "r"(a[2]), "r"(a[3]), "r"(b[0]), "r"(b[1]));
}

// ---------------------------------------------------------------------------
// Kernel 1: LayerNorm -> bf16 hi/lo split. One block per row, 256 threads.
// ---------------------------------------------------------------------------
__global__ __launch_bounds__(256)
void ln_kernel(const float* __restrict__ x,
               const float* __restrict__ w,
               const float* __restrict__ bvec,
               __nv_bfloat16* __restrict__ yhi,
               __nv_bfloat16* __restrict__ ylo)
{
    const int row = blockIdx.x;
    const int t = threadIdx.x;
    const float4 xv = ((const float4*)(x + (size_t)row * HH))[t];

    float s  = xv.x + xv.y + xv.z + xv.w;
    float ss = xv.x * xv.x + xv.y * xv.y + xv.z * xv.z + xv.w * xv.w;
    #pragma unroll
    for (int o = 16; o > 0; o >>= 1) {
        s  += __shfl_xor_sync(0xFFFFFFFFu, s,  o);
        ss += __shfl_xor_sync(0xFFFFFFFFu, ss, o);
    }
    __shared__ float rs[8], rss[8];
    __shared__ float smu, srstd;
    const int wid = t >> 5, lane = t & 31;
    if (lane == 0) { rs[wid] = s; rss[wid] = ss; }
    __syncthreads();
    if (t == 0) {
        float a = 0.f, b2 = 0.f;
        #pragma unroll
        for (int i = 0; i < 8; i++) { a += rs[i]; b2 += rss[i]; }
        const float mu = a * (1.0f / HH);
        float var = b2 * (1.0f / HH) - mu * mu;
        smu = mu;
        srstd = rsqrtf(var + 1e-12f);
    }
    __syncthreads();
    const float mu = smu, rstd = srstd;
    const float4 wv = ((const float4*)w)[t];
    const float4 bv = ((const float4*)bvec)[t];
    float v[4];
    v[0] = (xv.x - mu) * rstd * wv.x + bv.x;
    v[1] = (xv.y - mu) * rstd * wv.y + bv.y;
    v[2] = (xv.z - mu) * rstd * wv.z + bv.z;
    v[3] = (xv.w - mu) * rstd * wv.w + bv.w;
    __nv_bfloat16 hi[4], lo[4];
    #pragma unroll
    for (int i = 0; i < 4; i++) {
        hi[i] = __float2bfloat16_rn(v[i]);
        lo[i] = __float2bfloat16_rn(v[i] - __bfloat162float(hi[i]));
    }
    const size_t base = (size_t)row * HH + t * 4;
    *(uint64_t*)(yhi + base) = *(uint64_t*)hi;
    *(uint64_t*)(ylo + base) = *(uint64_t*)lo;
}

// ---------------------------------------------------------------------------
// Kernel: fp32 -> bf16 hi/lo split (weights)
// ---------------------------------------------------------------------------
__global__ __launch_bounds__(256)
void split_kernel(const float* __restrict__ x,
                  __nv_bfloat16* __restrict__ hi,
                  __nv_bfloat16* __restrict__ lo, int n4)
{
    const int i = blockIdx.x * 256 + threadIdx.x;
    if (i >= n4) return;
    const float4 v = ((const float4*)x)[i];
    __nv_bfloat16 h[4], l[4];
    const float vv[4] = {v.x, v.y, v.z, v.w};
    #pragma unroll
    for (int j = 0; j < 4; j++) {
        h[j] = __float2bfloat16_rn(vv[j]);
        l[j] = __float2bfloat16_rn(vv[j] - __bfloat162float(h[j]));
    }
    ((uint64_t*)hi)[i] = *(uint64_t*)h;
    ((uint64_t*)lo)[i] = *(uint64_t*)l;
}

// ---------------------------------------------------------------------------
// bf16 interleaved-split GEMM (HMMA): one K-sweep, 3 MMA terms per k-chunk
// (Ah·Bh + Ah·Bl + Al·Bh). 2-stage cp.async ring of 4 tiles per stage.
// Dynamic smem: 2 stages x 4 tiles x (128 x 40 bf16) = 81920 B.
// ---------------------------------------------------------------------------
template<bool SPLIT>
__global__ __launch_bounds__(256, 2)
void gemm_mma(const __nv_bfloat16* __restrict__ Ahi, const __nv_bfloat16* __restrict__ Alo,
              const __nv_bfloat16* __restrict__ Bhi, const __nv_bfloat16* __restrict__ Blo,
              const float* __restrict__ bias,
              float* __restrict__ F1, float* __restrict__ F2,
              float* __restrict__ C0,
              __nv_bfloat16* __restrict__ H0, __nv_bfloat16* __restrict__ L0,
              __nv_bfloat16* __restrict__ H1, __nv_bfloat16* __restrict__ L1,
              __nv_bfloat16* __restrict__ H2, __nv_bfloat16* __restrict__ L2,
              int K, int N)
{
    constexpr int BK = 32, STR = 40;
    constexpr int TILEB = 128 * STR * 2;     // 10240 B per tile
    constexpr int STAGE = 4 * TILEB;         // Ah, Al, Bh, Bl
    extern __shared__ char dsm[];
    const uint32_t sb = smem_u32(dsm);

    const int t = threadIdx.x;
    const int wid = t >> 5, lane = t & 31;
    const int warp_m = wid >> 2;
    const int warp_n = wid & 3;
    const int bm = blockIdx.y * 128;
    const int bn = blockIdx.x * 128;

    float acc[4][4][4];
    #pragma unroll
    for (int i = 0; i < 4; i++)
        #pragma unroll
        for (int j = 0; j < 4; j++)
            #pragma unroll
            for (int r = 0; r < 4; r++) acc[i][j][r] = 0.f;

    const int nkp = K / BK;

    const int r0 = t >> 2, ch = (t & 3) * 8;
    const uint32_t soff0 = (uint32_t)(r0 * STR + ch) * 2;
    const uint32_t soff1 = (uint32_t)((r0 + 64) * STR + ch) * 2;

    auto issue = [&](int i) {
        const uint32_t st = sb + (i & 1) * STAGE;
        const int k0 = i * BK;
        CP_ASYNC16(st + 0 * TILEB + soff0, Ahi + (size_t)(bm + r0) * K + k0 + ch);
        CP_ASYNC16(st + 0 * TILEB + soff1, Ahi + (size_t)(bm + r0 + 64) * K + k0 + ch);
        CP_ASYNC16(st + 1 * TILEB + soff0, Alo + (size_t)(bm + r0) * K + k0 + ch);
        CP_ASYNC16(st + 1 * TILEB + soff1, Alo + (size_t)(bm + r0 + 64) * K + k0 + ch);
        CP_ASYNC16(st + 2 * TILEB + soff0, Bhi + (size_t)(bn + r0) * K + k0 + ch);
        CP_ASYNC16(st + 2 * TILEB + soff1, Bhi + (size_t)(bn + r0 + 64) * K + k0 + ch);
        CP_ASYNC16(st + 3 * TILEB + soff0, Blo + (size_t)(bn + r0) * K + k0 + ch);
        CP_ASYNC16(st + 3 * TILEB + soff1, Blo + (size_t)(bn + r0 + 64) * K + k0 + ch);
        CP_COMMIT();
    };

    issue(0);
    for (int i = 0; i < nkp; i++) {
        CP_WAIT0();
        __syncthreads();
        if (i + 1 < nkp) issue(i + 1);
        const uint32_t st = sb + (i & 1) * STAGE;
        const uint32_t sAh = st;
        const uint32_t sAl = st + TILEB;
        const uint32_t sBh = st + 2 * TILEB;
        const uint32_t sBl = st + 3 * TILEB;

        #pragma unroll
        for (int ks = 0; ks < 2; ks++) {
            uint32_t af[4][4];
            uint32_t bh[2][4], bl[2][4];
            // B fragments (hi & lo), 2 n-tiles per x4 load
            #pragma unroll
            for (int nt2 = 0; nt2 < 2; nt2++) {
                const int row = warp_n * 32 + nt2 * 16 + ((lane >> 4) * 8) + (lane & 7);
                const int kc = ks * 16 + (((lane >> 3) & 1) * 8);
                const uint32_t off = (uint32_t)(row * STR + kc) * 2;
                ldm_x4(bh[nt2], sBh + off);
                ldm_x4(bl[nt2], sBl + off);
            }
            // Pass 1+2: Ah x Bh, Ah x Bl
            #pragma unroll
            for (int mt = 0; mt < 4; mt++) {
                const int row = warp_m * 64 + mt * 16 + (lane & 15);
                const int kc = ks * 16 + ((lane >> 4) * 8);
                ldm_x4(af[mt], sAh + (uint32_t)(row * STR + kc) * 2);
            }
            #pragma unroll
            for (int mt = 0; mt < 4; mt++)
                #pragma unroll
                for (int nt = 0; nt < 4; nt++) {
                    mma16816(acc[mt][nt], af[mt], &bh[nt >> 1][(nt & 1) * 2]);
                    mma16816(acc[mt][nt], af[mt], &bl[nt >> 1][(nt & 1) * 2]);
                }
            // Pass 3: Al x Bh (reuse af registers)
            #pragma unroll
            for (int mt = 0; mt < 4; mt++) {
                const int row = warp_m * 64 + mt * 16 + (lane & 15);
                const int kc = ks * 16 + ((lane >> 4) * 8);
                ldm_x4(af[mt], sAl + (uint32_t)(row * STR + kc) * 2);
            }
            #pragma unroll
            for (int mt = 0; mt < 4; mt++)
                #pragma unroll
                for (int nt = 0; nt < 4; nt++)
                    mma16816(acc[mt][nt], af[mt], &bh[nt >> 1][(nt & 1) * 2]);
        }
    }

    // Epilogue
    const int sec = bn >> 10;
    float* Fsec = nullptr;
    __nv_bfloat16 *Hsec = nullptr, *Lsec = nullptr;
    int cstride = N;
    if (SPLIT) {
        Fsec = (sec == 0) ? nullptr : ((sec == 1) ? F1 : F2);
        Hsec = (sec == 0) ? H0 : ((sec == 1) ? H1 : H2);
        Lsec = (sec == 0) ? L0 : ((sec == 1) ? L1 : L2);
        cstride = 1024;
    }

    #pragma unroll
    for (int mt = 0; mt < 4; mt++) {
        const int m0 = bm + warp_m * 64 + mt * 16 + (lane >> 2);
        #pragma unroll
        for (int nt = 0; nt < 4; nt++) {
            const int n0 = bn + warp_n * 32 + nt * 8 + (lane & 3) * 2;
            float b0 = 0.f, b1 = 0.f;
            if (bias) { b0 = bias[n0]; b1 = bias[n0 + 1]; }
            const int col = SPLIT ? (n0 & 1023) : n0;
            float2 v0 = { acc[mt][nt][0] + b0, acc[mt][nt][1] + b1 };
            float2 v1 = { acc[mt][nt][2] + b0, acc[mt][nt][3] + b1 };
            if (SPLIT) {
                if (Fsec) {
                    *(float2*)(Fsec + (size_t)m0 * cstride + col)       = v0;
                    *(float2*)(Fsec + (size_t)(m0 + 8) * cstride + col) = v1;
                }
                __nv_bfloat162 h0 = __float22bfloat162_rn(v0);
                __nv_bfloat162 l0;
                l0.x = __float2bfloat16_rn(v0.x - __bfloat162float(h0.x));
                l0.y = __float2bfloat16_rn(v0.y - __bfloat162float(h0.y));
                __nv_bfloat162 h1 = __float22bfloat162_rn(v1);
                __nv_bfloat162 l1;
                l1.x = __float2bfloat16_rn(v1.x - __bfloat162float(h1.x));
                l1.y = __float2bfloat16_rn(v1.y - __bfloat162float(h1.y));
                *(__nv_bfloat162*)(Hsec + (size_t)m0 * 1024 + col)       = h0;
                *(__nv_bfloat162*)(Lsec + (size_t)m0 * 1024 + col)       = l0;
                *(__nv_bfloat162*)(Hsec + (size_t)(m0 + 8) * 1024 + col) = h1;
                *(__nv_bfloat162*)(Lsec + (size_t)(m0 + 8) * 1024 + col) = l1;
            } else {
                *(float2*)(C0 + (size_t)m0 * cstride + col)       = v0;
                *(float2*)(C0 + (size_t)(m0 + 8) * cstride + col) = v1;
            }
        }
    }
}

// ---------------------------------------------------------------------------
// Flash attention on HMMA, 2-stage cp.async K/V ring, x4 fragment loads.
// CTA: 64 q-rows, 4 warps. Dynamic smem: 2 x (4 tiles 64x72 bf16 + mask) = 74240 B.
// ---------------------------------------------------------------------------
__global__ __launch_bounds__(128)
void attn_mma(const __nv_bfloat16* __restrict__ Qh, const __nv_bfloat16* __restrict__ Ql,
              const __nv_bfloat16* __restrict__ Kh, const __nv_bfloat16* __restrict__ Kl,
              const __nv_bfloat16* __restrict__ Vh, const __nv_bfloat16* __restrict__ Vl,
              const float* __restrict__ mask, float* __restrict__ Ctx,
              __nv_bfloat16* __restrict__ Chi, __nv_bfloat16* __restrict__ Clo)
{
    constexpr int STR = 72;
    constexpr int TILE = 64 * STR * 2;          // 9216 B
    constexpr int STAGE = 4 * TILE + 256;       // + mask, 37120 B
    extern __shared__ char dsm[];
    const uint32_t sb = smem_u32(dsm);

    const int b = blockIdx.z, h = blockIdx.y, qt = blockIdx.x;
    const int t = threadIdx.x, wid = t >> 5, lane = t & 31;
    const float scale = 0.125f;
    const int nkt = SS / 64;

    // ---- stage Q tile (64x64 hi/lo) into stage-0 region and load fragments
    {
        const size_t qbase = (size_t)(b * SS + qt * 64) * HH + h * DHEAD;
        #pragma unroll
        for (int i = 0; i < 4; i++) {
            const int id = t + i * 128;
            const int r = id >> 3, c = (id & 7) * 8;
            *(uint4*)(dsm + (r * STR + c) * 2)        = *(const uint4*)(Qh + qbase + (size_t)r * HH + c);
            *(uint4*)(dsm + TILE + (r * STR + c) * 2) = *(const uint4*)(Ql + qbase + (size_t)r * HH + c);
        }
    }
    __syncthreads();
    uint32_t qhf[4][4], qlf[4][4];
    {
        const int row = wid * 16 + (lane & 15);
        #pragma unroll
        for (int ks = 0; ks < 4; ks++) {
            const int kc = ks * 16 + ((lane >> 4) * 8);
            ldm_x4(qhf[ks], sb + (uint32_t)(row * STR + kc) * 2);
            ldm_x4(qlf[ks], sb + TILE + (uint32_t)(row * STR + kc) * 2);
        }
    }
    __syncthreads();

    // ---- cp.async issue of K/V/mask for tile kt into stage kt&1
    auto issue = [&](int kt) {
        const int s = kt & 1;
        const uint32_t st = sb + s * STAGE;
        const size_t kbase = (size_t)(b * SS + kt * 64) * HH + h * DHEAD;
        const __nv_bfloat16* tp0 = Kh; const __nv_bfloat16* tp1 = Kl;
        const __nv_bfloat16* tp2 = Vh; const __nv_bfloat16* tp3 = Vl;
        #pragma unroll
        for (int i = 0; i < 16; i++) {
            const int id = t + i * 128;
            const int tile = id >> 9;
            const int r = (id >> 3) & 63, c = (id & 7) * 8;
            const __nv_bfloat16* tp = (tile == 0) ? tp0 : ((tile == 1) ? tp1 : ((tile == 2) ? tp2 : tp3));
            CP_ASYNC16(st + tile * TILE + (uint32_t)(r * STR + c) * 2,
                       tp + kbase + (size_t)r * HH + c);
        }
        if (t < 16) CP_ASYNC16(st + 4 * TILE + t * 16, mask + b * SS + kt * 64 + t * 4);
        CP_COMMIT();
    };

    // ---- flash state
    float o[8][4];
    #pragma unroll
    for (int nt = 0; nt < 8; nt++)
        #pragma unroll
        for (int r = 0; r < 4; r++) o[nt][r] = 0.f;
    float m0 = -INFINITY, m1 = -INFINITY;
    float l0 = 0.f, l1 = 0.f;

    issue(0);
    for (int kt = 0; kt < nkt; kt++) {
        if (kt + 1 < nkt) issue(kt + 1);
        if (kt + 1 < nkt) { CP_WAIT1(); } else { CP_WAIT0(); }
        __syncthreads();

        const int s = kt & 1;
        const uint32_t sKh = sb + s * STAGE;
        const uint32_t sKl = sKh + TILE;
        const uint32_t sVh = sKh + 2 * TILE;
        const uint32_t sVl = sKh + 3 * TILE;
        const float* mskp = (const float*)(dsm + s * STAGE + 4 * TILE);

        // ---- S = Qh@Kh^T + Qh@Kl^T + Ql@Kh^T  (16 x 64 per warp)
        float sacc[8][4];
        #pragma unroll
        for (int nt = 0; nt < 8; nt++)
            #pragma unroll
            for (int r = 0; r < 4; r++) sacc[nt][r] = 0.f;

        #pragma unroll
        for (int ks = 0; ks < 4; ks++) {
            #pragma unroll
            for (int nt2 = 0; nt2 < 4; nt2++) {
                uint32_t bh[4], bl[4];
                const int row = nt2 * 16 + ((lane >> 4) * 8) + (lane & 7);
                const int kc = ks * 16 + (((lane >> 3) & 1) * 8);
                const uint32_t off = (uint32_t)(row * STR + kc) * 2;
                ldm_x4(bh, sKh + off);
                ldm_x4(bl, sKl + off);
                mma16816(sacc[2 * nt2],     qhf[ks], &bh[0]);
                mma16816(sacc[2 * nt2],     qhf[ks], &bl[0]);
                mma16816(sacc[2 * nt2],     qlf[ks], &bh[0]);
                mma16816(sacc[2 * nt2 + 1], qhf[ks], &bh[2]);
                mma16816(sacc[2 * nt2 + 1], qhf[ks], &bl[2]);
                mma16816(sacc[2 * nt2 + 1], qlf[ks], &bh[2]);
            }
        }

        // ---- softmax (rows r=lane/4 and r+8; cols per nt: nt*8+(lane&3)*2,+1)
        float nm0 = m0, nm1 = m1;
        #pragma unroll
        for (int nt = 0; nt < 8; nt++) {
            const int c0 = nt * 8 + (lane & 3) * 2;
            const float mk0 = mskp[c0], mk1 = mskp[c0 + 1];
            sacc[nt][0] = sacc[nt][0] * scale + mk0;
            sacc[nt][1] = sacc[nt][1] * scale + mk1;
            sacc[nt][2] = sacc[nt][2] * scale + mk0;
            sacc[nt][3] = sacc[nt][3] * scale + mk1;
            nm0 = fmaxf(nm0, fmaxf(sacc[nt][0], sacc[nt][1]));
            nm1 = fmaxf(nm1, fmaxf(sacc[nt][2], sacc[nt][3]));
        }
        nm0 = fmaxf(nm0, __shfl_xor_sync(0xFFFFFFFFu, nm0, 1));
        nm0 = fmaxf(nm0, __shfl_xor_sync(0xFFFFFFFFu, nm0, 2));
        nm1 = fmaxf(nm1, __shfl_xor_sync(0xFFFFFFFFu, nm1, 1));
        nm1 = fmaxf(nm1, __shfl_xor_sync(0xFFFFFFFFu, nm1, 2));

        const float cr0 = __expf(m0 - nm0);
        const float cr1 = __expf(m1 - nm1);
        l0 *= cr0; l1 *= cr1;
        #pragma unroll
        for (int nt = 0; nt < 8; nt++) {
            o[nt][0] *= cr0; o[nt][1] *= cr0;
            o[nt][2] *= cr1; o[nt][3] *= cr1;
        }
        #pragma unroll
        for (int nt = 0; nt < 8; nt++) {
            sacc[nt][0] = __expf(sacc[nt][0] - nm0);
            sacc[nt][1] = __expf(sacc[nt][1] - nm0);
            sacc[nt][2] = __expf(sacc[nt][2] - nm1);
            sacc[nt][3] = __expf(sacc[nt][3] - nm1);
            l0 += sacc[nt][0] + sacc[nt][1];
            l1 += sacc[nt][2] + sacc[nt][3];
        }
        m0 = nm0; m1 = nm1;

        // ---- PV: per k-step ks, P A-frag from S n-tiles (2ks, 2ks+1)
        #pragma unroll
        for (int ks = 0; ks < 4; ks++) {
            uint32_t ph[4], pl[4];
            {
                const float* sa = sacc[2 * ks];
                const float* sbp = sacc[2 * ks + 1];
                __nv_bfloat162 hh, ll;
                float2 f;
                f.x = sa[0]; f.y = sa[1];
                hh = __float22bfloat162_rn(f);
                ll.x = __float2bfloat16_rn(f.x - __bfloat162float(hh.x));
                ll.y = __float2bfloat16_rn(f.y - __bfloat162float(hh.y));
                ph[0] = *(uint32_t*)&hh; pl[0] = *(uint32_t*)&ll;
                f.x = sa[2]; f.y = sa[3];
                hh = __float22bfloat162_rn(f);
                ll.x = __float2bfloat16_rn(f.x - __bfloat162float(hh.x));
                ll.y = __float2bfloat16_rn(f.y - __bfloat162float(hh.y));
                ph[1] = *(uint32_t*)&hh; pl[1] = *(uint32_t*)&ll;
                f.x = sbp[0]; f.y = sbp[1];
                hh = __float22bfloat162_rn(f);
                ll.x = __float2bfloat16_rn(f.x - __bfloat162float(hh.x));
                ll.y = __float2bfloat16_rn(f.y - __bfloat162float(hh.y));
                ph[2] = *(uint32_t*)&hh; pl[2] = *(uint32_t*)&ll;
                f.x = sbp[2]; f.y = sbp[3];
                hh = __float22bfloat162_rn(f);
                ll.x = __float2bfloat16_rn(f.x - __bfloat162float(hh.x));
                ll.y = __float2bfloat16_rn(f.y - __bfloat162float(hh.y));
                ph[3] = *(uint32_t*)&hh; pl[3] = *(uint32_t*)&ll;
            }
            #pragma unroll
            for (int nt2 = 0; nt2 < 4; nt2++) {
                uint32_t vh[4], vl[4];
                const int row = ks * 16 + (((lane >> 3) & 1) * 8) + (lane & 7);
                const int col = nt2 * 16 + ((lane >> 4) * 8);
                const uint32_t off = (uint32_t)(row * STR + col) * 2;
                ldm_x4t(vh, sVh + off);
                ldm_x4t(vl, sVl + off);
                mma16816(o[2 * nt2],     ph, &vh[0]);
                mma16816(o[2 * nt2],     ph, &vl[0]);
                mma16816(o[2 * nt2],     pl, &vh[0]);
                mma16816(o[2 * nt2 + 1], ph, &vh[2]);
                mma16816(o[2 * nt2 + 1], ph, &vl[2]);
                mma16816(o[2 * nt2 + 1], pl, &vh[2]);
            }
        }
        __syncthreads();
    }

    // ---- final reduce + write
    l0 += __shfl_xor_sync(0xFFFFFFFFu, l0, 1);
    l0 += __shfl_xor_sync(0xFFFFFFFFu, l0, 2);
    l1 += __shfl_xor_sync(0xFFFFFFFFu, l1, 1);
    l1 += __shfl_xor_sync(0xFFFFFFFFu, l1, 2);
    const float inv0 = 1.0f / l0;
    const float inv1 = 1.0f / l1;

    const int grow0 = b * SS + qt * 64 + wid * 16 + (lane >> 2);
    const int grow1 = grow0 + 8;
    #pragma unroll
    for (int nt = 0; nt < 8; nt++) {
        const int col = h * DHEAD + nt * 8 + (lane & 3) * 2;
        float2 v0 = { o[nt][0] * inv0, o[nt][1] * inv0 };
        float2 v1 = { o[nt][2] * inv1, o[nt][3] * inv1 };
        *(float2*)(Ctx + (size_t)grow0 * HH + col) = v0;
        *(float2*)(Ctx + (size_t)grow1 * HH + col) = v1;
        __nv_bfloat162 h0 = __float22bfloat162_rn(v0);
        __nv_bfloat162 l0b;
        l0b.x = __float2bfloat16_rn(v0.x - __bfloat162float(h0.x));
        l0b.y = __float2bfloat16_rn(v0.y - __bfloat162float(h0.y));
        __nv_bfloat162 h1 = __float22bfloat162_rn(v1);
        __nv_bfloat162 l1b;
        l1b.x = __float2bfloat16_rn(v1.x - __bfloat162float(h1.x));
        l1b.y = __float2bfloat16_rn(v1.y - __bfloat162float(h1.y));
        *(__nv_bfloat162*)(Chi + (size_t)grow0 * HH + col) = h0;
        *(__nv_bfloat162*)(Clo + (size_t)grow0 * HH + col) = l0b;
        *(__nv_bfloat162*)(Chi + (size_t)grow1 * HH + col) = h1;
        *(__nv_bfloat162*)(Clo + (size_t)grow1 * HH + col) = l1b;
    }
}

// ---------------------------------------------------------------------------
// Launch
// ---------------------------------------------------------------------------
extern "C" void kernel_launch(void* const* d_in, const int* in_sizes, int n_in,
                              void* d_out, int out_size)
{
    const float* input = (const float*)d_in[0];
    const float* mask  = (const float*)d_in[1];
    const float* nw    = (const float*)d_in[2];
    const float* nb    = (const float*)d_in[3];
    const float* qkvw  = (const float*)d_in[4];
    const float* qkvb  = (const float*)d_in[5];
    const float* ow    = (const float*)d_in[6];

    float* out     = (float*)d_out;
    float* key_out = out + (size_t)TENSOR_ELEMS;
    float* val_out = out + (size_t)2 * TENSOR_ELEMS;
    float* ctx_out = out + (size_t)3 * TENSOR_ELEMS;

    __nv_bfloat16 *a_hi, *a_lo, *w_hi, *w_lo, *ow_hi, *ow_lo;
    __nv_bfloat16 *q_hi, *q_lo, *k_hi, *k_lo, *v_hi, *v_lo, *c_hi, *c_lo;
    cudaGetSymbolAddress((void**)&a_hi, g_a_hi);
    cudaGetSymbolAddress((void**)&a_lo, g_a_lo);
    cudaGetSymbolAddress((void**)&w_hi, g_w_hi);
    cudaGetSymbolAddress((void**)&w_lo, g_w_lo);
    cudaGetSymbolAddress((void**)&ow_hi, g_ow_hi);
    cudaGetSymbolAddress((void**)&ow_lo, g_ow_lo);
    cudaGetSymbolAddress((void**)&q_hi, g_q_hi);
    cudaGetSymbolAddress((void**)&q_lo, g_q_lo);
    cudaGetSymbolAddress((void**)&k_hi, g_k_hi);
    cudaGetSymbolAddress((void**)&k_lo, g_k_lo);
    cudaGetSymbolAddress((void**)&v_hi, g_v_hi);
    cudaGetSymbolAddress((void**)&v_lo, g_v_lo);
    cudaGetSymbolAddress((void**)&c_hi, g_c_hi);
    cudaGetSymbolAddress((void**)&c_lo, g_c_lo);

    const int GEMM_DYN = 2 * 4 * 128 * 40 * 2;         // 81920
    const int ATTN_DYN = 2 * (4 * 64 * 72 * 2 + 256);  // 74240
    cudaFuncSetAttribute(gemm_mma<true>,  cudaFuncAttributeMaxDynamicSharedMemorySize, GEMM_DYN);
    cudaFuncSetAttribute(gemm_mma<false>, cudaFuncAttributeMaxDynamicSharedMemorySize, GEMM_DYN);
    cudaFuncSetAttribute(attn_mma, cudaFuncAttributeMaxDynamicSharedMemorySize, ATTN_DYN);

    // 1) LayerNorm -> bf16 split
    ln_kernel<<<MROWS, 256>>>(input, nw, nb, a_hi, a_lo);

    // 2) Weight splits
    split_kernel<<<(3 * HH * HH / 4 + 255) / 256, 256>>>(qkvw, w_hi, w_lo, 3 * HH * HH / 4);
    split_kernel<<<(HH * HH / 4 + 255) / 256, 256>>>(ow, ow_hi, ow_lo, HH * HH / 4);

    // 3) QKV GEMM: fp32 K/V outputs + bf16 hi/lo Q/K/V scratch
    {
        dim3 grid(3072 / 128, MROWS / 128);
        gemm_mma<true><<<grid, 256, GEMM_DYN>>>(a_hi, a_lo, w_hi, w_lo, qkvb,
                                                key_out, val_out, nullptr,
                                                q_hi, q_lo, k_hi, k_lo, v_hi, v_lo,
                                                HH, 3 * HH);
    }

    // 4) Flash attention (HMMA) -> ctx fp32 + ctx bf16 hi/lo
    {
        dim3 grid(SS / 64, NHEADS, BB);
        attn_mma<<<grid, 128, ATTN_DYN>>>(q_hi, q_lo, k_hi, k_lo, v_hi, v_lo,
                                          mask, ctx_out, c_hi, c_lo);
    }

    // 5) Output projection
    {
        dim3 grid(HH / 128, MROWS / 128);
        gemm_mma<false><<<grid, 256, GEMM_DYN>>>(c_hi, c_lo, ow_hi, ow_lo, nullptr,
                                                 nullptr, nullptr, out,
                                                 nullptr, nullptr, nullptr, nullptr, nullptr, nullptr,
                                                 HH, HH);
    }
}

// round 16
// speedup vs baseline: 3.6716x; 1.0246x over previous
#include <cuda_runtime.h>
#include <cuda_bf16.h>
#include <math.h>
#include <stdint.h>

// Problem constants (fixed by the reference)
#define BB 4
#define SS 2048
#define HH 1024
#define NHEADS 16
#define DHEAD 64
#define MROWS (BB * SS)            // 8192
#define TENSOR_ELEMS (MROWS * HH)  // 8,388,608 per output tensor

// ---------------------------------------------------------------------------
// Scratch (__device__ globals; no runtime allocation allowed)
// ---------------------------------------------------------------------------
__device__ __nv_bfloat16 g_a_hi[MROWS * HH];
__device__ __nv_bfloat16 g_a_lo[MROWS * HH];
__device__ __nv_bfloat16 g_w_hi[3 * HH * HH];
__device__ __nv_bfloat16 g_w_lo[3 * HH * HH];
__device__ __nv_bfloat16 g_ow_hi[HH * HH];
__device__ __nv_bfloat16 g_ow_lo[HH * HH];
__device__ __nv_bfloat16 g_q_hi[MROWS * HH];
__device__ __nv_bfloat16 g_q_lo[MROWS * HH];
__device__ __nv_bfloat16 g_k_hi[MROWS * HH];
__device__ __nv_bfloat16 g_k_lo[MROWS * HH];
__device__ __nv_bfloat16 g_v_hi[MROWS * HH];
__device__ __nv_bfloat16 g_v_lo[MROWS * HH];
__device__ __nv_bfloat16 g_c_hi[MROWS * HH];
__device__ __nv_bfloat16 g_c_lo[MROWS * HH];

// ---------------------------------------------------------------------------
// PTX helpers — target-portable (sm_80+)
// ---------------------------------------------------------------------------
__device__ __forceinline__ uint32_t smem_u32(const void* p) {
    uint32_t a;
    asm("{ .reg .u64 t; cvta.to.shared.u64 t, %1; cvt.u32.u64 %0, t; }" : "=r"(a) : "l"(p));
    return a;
}
#define CP_ASYNC16(dst, src) \
    asm volatile("cp.async.cg.shared.global [%0], [%1], 16;" :: "r"(dst), "l"(src))
#define CP_COMMIT() asm volatile("cp.async.commit_group;" ::: "memory")
#define CP_WAIT0()  asm volatile("cp.async.wait_group 0;" ::: "memory")
#define CP_WAIT1()  asm volatile("cp.async.wait_group 1;" ::: "memory")

__device__ __forceinline__ void ldm_x4(uint32_t* r, uint32_t addr) {
    asm volatile("ldmatrix.sync.aligned.m8n8.x4.shared.b16 {%0,%1,%2,%3}, [%4];"
                 : "=r"(r[0]), "=r"(r[1]), "=r"(r[2]), "=r"(r[3]) : "r"(addr));
}
__device__ __forceinline__ void ldm_x4t(uint32_t* r, uint32_t addr) {
    asm volatile("ldmatrix.sync.aligned.m8n8.x4.trans.shared.b16 {%0,%1,%2,%3}, [%4];"
                 : "=r"(r[0]), "=r"(r[1]), "=r"(r[2]), "=r"(r[3]) : "r"(addr));
}
__device__ __forceinline__ void mma16816(float* c, const uint32_t* a, const uint32_t* b) {
    asm volatile(
        "mma.sync.aligned.m16n8k16.row.col.f32.bf16.bf16.f32 "
        "{%0,%1,%2,%3}, {%4,%5,%6,%7}, {%8,%9}, {%0,%1,%2,%3};"
        : "+f"(c[0]), "+f"(c[1]), "+f"(c[2]), "+f"(c[3])
        : "r"(a[0]), "r"(a[1]), "r"(a[2]), "r"(a[3]), "r"(b[0]), "r"(b[1]));
}

// ---------------------------------------------------------------------------
// Kernel 1: LayerNorm -> bf16 hi/lo split. One block per row, 256 threads.
// ---------------------------------------------------------------------------
__global__ __launch_bounds__(256)
void ln_kernel(const float* __restrict__ x,
               const float* __restrict__ w,
               const float* __restrict__ bvec,
               __nv_bfloat16* __restrict__ yhi,
               __nv_bfloat16* __restrict__ ylo)
{
    const int row = blockIdx.x;
    const int t = threadIdx.x;
    const float4 xv = ((const float4*)(x + (size_t)row * HH))[t];

    float s  = xv.x + xv.y + xv.z + xv.w;
    float ss = xv.x * xv.x + xv.y * xv.y + xv.z * xv.z + xv.w * xv.w;
    #pragma unroll
    for (int o = 16; o > 0; o >>= 1) {
        s  += __shfl_xor_sync(0xFFFFFFFFu, s,  o);
        ss += __shfl_xor_sync(0xFFFFFFFFu, ss, o);
    }
    __shared__ float rs[8], rss[8];
    __shared__ float smu, srstd;
    const int wid = t >> 5, lane = t & 31;
    if (lane == 0) { rs[wid] = s; rss[wid] = ss; }
    __syncthreads();
    if (t == 0) {
        float a = 0.f, b2 = 0.f;
        #pragma unroll
        for (int i = 0; i < 8; i++) { a += rs[i]; b2 += rss[i]; }
        const float mu = a * (1.0f / HH);
        float var = b2 * (1.0f / HH) - mu * mu;
        smu = mu;
        srstd = rsqrtf(var + 1e-12f);
    }
    __syncthreads();
    const float mu = smu, rstd = srstd;
    const float4 wv = ((const float4*)w)[t];
    const float4 bv = ((const float4*)bvec)[t];
    float v[4];
    v[0] = (xv.x - mu) * rstd * wv.x + bv.x;
    v[1] = (xv.y - mu) * rstd * wv.y + bv.y;
    v[2] = (xv.z - mu) * rstd * wv.z + bv.z;
    v[3] = (xv.w - mu) * rstd * wv.w + bv.w;
    __nv_bfloat16 hi[4], lo[4];
    #pragma unroll
    for (int i = 0; i < 4; i++) {
        hi[i] = __float2bfloat16_rn(v[i]);
        lo[i] = __float2bfloat16_rn(v[i] - __bfloat162float(hi[i]));
    }
    const size_t base = (size_t)row * HH + t * 4;
    *(uint64_t*)(yhi + base) = *(uint64_t*)hi;
    *(uint64_t*)(ylo + base) = *(uint64_t*)lo;
}

// ---------------------------------------------------------------------------
// Kernel: fp32 -> bf16 hi/lo split (weights)
// ---------------------------------------------------------------------------
__global__ __launch_bounds__(256)
void split_kernel(const float* __restrict__ x,
                  __nv_bfloat16* __restrict__ hi,
                  __nv_bfloat16* __restrict__ lo, int n4)
{
    const int i = blockIdx.x * 256 + threadIdx.x;
    if (i >= n4) return;
    const float4 v = ((const float4*)x)[i];
    __nv_bfloat16 h[4], l[4];
    const float vv[4] = {v.x, v.y, v.z, v.w};
    #pragma unroll
    for (int j = 0; j < 4; j++) {
        h[j] = __float2bfloat16_rn(vv[j]);
        l[j] = __float2bfloat16_rn(vv[j] - __bfloat162float(h[j]));
    }
    ((uint64_t*)hi)[i] = *(uint64_t*)h;
    ((uint64_t*)lo)[i] = *(uint64_t*)l;
}

// ---------------------------------------------------------------------------
// bf16 interleaved-split GEMM (HMMA): one K-sweep, 3 MMA terms per k-chunk
// (Ah·Bh + Ah·Bl + Al·Bh). 2-stage cp.async ring of 4 tiles per stage.
// Dynamic smem: 2 stages x 4 tiles x (128 x 40 bf16) = 81920 B.
// ---------------------------------------------------------------------------
template<bool SPLIT>
__global__ __launch_bounds__(256, 2)
void gemm_mma(const __nv_bfloat16* __restrict__ Ahi, const __nv_bfloat16* __restrict__ Alo,
              const __nv_bfloat16* __restrict__ Bhi, const __nv_bfloat16* __restrict__ Blo,
              const float* __restrict__ bias,
              float* __restrict__ F1, float* __restrict__ F2,
              float* __restrict__ C0,
              __nv_bfloat16* __restrict__ H0, __nv_bfloat16* __restrict__ L0,
              __nv_bfloat16* __restrict__ H1, __nv_bfloat16* __restrict__ L1,
              __nv_bfloat16* __restrict__ H2, __nv_bfloat16* __restrict__ L2,
              int K, int N)
{
    constexpr int BK = 32, STR = 40;
    constexpr int TILEB = 128 * STR * 2;     // 10240 B per tile
    constexpr int STAGE = 4 * TILEB;         // Ah, Al, Bh, Bl
    extern __shared__ char dsm[];
    const uint32_t sb = smem_u32(dsm);

    const int t = threadIdx.x;
    const int wid = t >> 5, lane = t & 31;
    const int warp_m = wid >> 2;
    const int warp_n = wid & 3;
    const int bm = blockIdx.y * 128;
    const int bn = blockIdx.x * 128;

    float acc[4][4][4];
    #pragma unroll
    for (int i = 0; i < 4; i++)
        #pragma unroll
        for (int j = 0; j < 4; j++)
            #pragma unroll
            for (int r = 0; r < 4; r++) acc[i][j][r] = 0.f;

    const int nkp = K / BK;

    const int r0 = t >> 2, ch = (t & 3) * 8;
    const uint32_t soff0 = (uint32_t)(r0 * STR + ch) * 2;
    const uint32_t soff1 = (uint32_t)((r0 + 64) * STR + ch) * 2;

    auto issue = [&](int i) {
        const uint32_t st = sb + (i & 1) * STAGE;
        const int k0 = i * BK;
        CP_ASYNC16(st + 0 * TILEB + soff0, Ahi + (size_t)(bm + r0) * K + k0 + ch);
        CP_ASYNC16(st + 0 * TILEB + soff1, Ahi + (size_t)(bm + r0 + 64) * K + k0 + ch);
        CP_ASYNC16(st + 1 * TILEB + soff0, Alo + (size_t)(bm + r0) * K + k0 + ch);
        CP_ASYNC16(st + 1 * TILEB + soff1, Alo + (size_t)(bm + r0 + 64) * K + k0 + ch);
        CP_ASYNC16(st + 2 * TILEB + soff0, Bhi + (size_t)(bn + r0) * K + k0 + ch);
        CP_ASYNC16(st + 2 * TILEB + soff1, Bhi + (size_t)(bn + r0 + 64) * K + k0 + ch);
        CP_ASYNC16(st + 3 * TILEB + soff0, Blo + (size_t)(bn + r0) * K + k0 + ch);
        CP_ASYNC16(st + 3 * TILEB + soff1, Blo + (size_t)(bn + r0 + 64) * K + k0 + ch);
        CP_COMMIT();
    };

    issue(0);
    for (int i = 0; i < nkp; i++) {
        CP_WAIT0();
        __syncthreads();
        if (i + 1 < nkp) issue(i + 1);
        const uint32_t st = sb + (i & 1) * STAGE;
        const uint32_t sAh = st;
        const uint32_t sAl = st + TILEB;
        const uint32_t sBh = st + 2 * TILEB;
        const uint32_t sBl = st + 3 * TILEB;

        #pragma unroll
        for (int ks = 0; ks < 2; ks++) {
            uint32_t af[4][4];
            uint32_t bh[2][4], bl[2][4];
            // B fragments (hi & lo), 2 n-tiles per x4 load
            #pragma unroll
            for (int nt2 = 0; nt2 < 2; nt2++) {
                const int row = warp_n * 32 + nt2 * 16 + ((lane >> 4) * 8) + (lane & 7);
                const int kc = ks * 16 + (((lane >> 3) & 1) * 8);
                const uint32_t off = (uint32_t)(row * STR + kc) * 2;
                ldm_x4(bh[nt2], sBh + off);
                ldm_x4(bl[nt2], sBl + off);
            }
            // Pass 1+2: Ah x Bh, Ah x Bl
            #pragma unroll
            for (int mt = 0; mt < 4; mt++) {
                const int row = warp_m * 64 + mt * 16 + (lane & 15);
                const int kc = ks * 16 + ((lane >> 4) * 8);
                ldm_x4(af[mt], sAh + (uint32_t)(row * STR + kc) * 2);
            }
            #pragma unroll
            for (int mt = 0; mt < 4; mt++)
                #pragma unroll
                for (int nt = 0; nt < 4; nt++) {
                    mma16816(acc[mt][nt], af[mt], &bh[nt >> 1][(nt & 1) * 2]);
                    mma16816(acc[mt][nt], af[mt], &bl[nt >> 1][(nt & 1) * 2]);
                }
            // Pass 3: Al x Bh (reuse af registers)
            #pragma unroll
            for (int mt = 0; mt < 4; mt++) {
                const int row = warp_m * 64 + mt * 16 + (lane & 15);
                const int kc = ks * 16 + ((lane >> 4) * 8);
                ldm_x4(af[mt], sAl + (uint32_t)(row * STR + kc) * 2);
            }
            #pragma unroll
            for (int mt = 0; mt < 4; mt++)
                #pragma unroll
                for (int nt = 0; nt < 4; nt++)
                    mma16816(acc[mt][nt], af[mt], &bh[nt >> 1][(nt & 1) * 2]);
        }
    }

    // Epilogue
    const int sec = bn >> 10;
    float* Fsec = nullptr;
    __nv_bfloat16 *Hsec = nullptr, *Lsec = nullptr;
    int cstride = N;
    if (SPLIT) {
        Fsec = (sec == 0) ? nullptr : ((sec == 1) ? F1 : F2);
        Hsec = (sec == 0) ? H0 : ((sec == 1) ? H1 : H2);
        Lsec = (sec == 0) ? L0 : ((sec == 1) ? L1 : L2);
        cstride = 1024;
    }

    #pragma unroll
    for (int mt = 0; mt < 4; mt++) {
        const int m0 = bm + warp_m * 64 + mt * 16 + (lane >> 2);
        #pragma unroll
        for (int nt = 0; nt < 4; nt++) {
            const int n0 = bn + warp_n * 32 + nt * 8 + (lane & 3) * 2;
            float b0 = 0.f, b1 = 0.f;
            if (bias) { b0 = bias[n0]; b1 = bias[n0 + 1]; }
            const int col = SPLIT ? (n0 & 1023) : n0;
            float2 v0 = { acc[mt][nt][0] + b0, acc[mt][nt][1] + b1 };
            float2 v1 = { acc[mt][nt][2] + b0, acc[mt][nt][3] + b1 };
            if (SPLIT) {
                if (Fsec) {
                    *(float2*)(Fsec + (size_t)m0 * cstride + col)       = v0;
                    *(float2*)(Fsec + (size_t)(m0 + 8) * cstride + col) = v1;
                }
                __nv_bfloat162 h0 = __float22bfloat162_rn(v0);
                __nv_bfloat162 l0;
                l0.x = __float2bfloat16_rn(v0.x - __bfloat162float(h0.x));
                l0.y = __float2bfloat16_rn(v0.y - __bfloat162float(h0.y));
                __nv_bfloat162 h1 = __float22bfloat162_rn(v1);
                __nv_bfloat162 l1;
                l1.x = __float2bfloat16_rn(v1.x - __bfloat162float(h1.x));
                l1.y = __float2bfloat16_rn(v1.y - __bfloat162float(h1.y));
                *(__nv_bfloat162*)(Hsec + (size_t)m0 * 1024 + col)       = h0;
                *(__nv_bfloat162*)(Lsec + (size_t)m0 * 1024 + col)       = l0;
                *(__nv_bfloat162*)(Hsec + (size_t)(m0 + 8) * 1024 + col) = h1;
                *(__nv_bfloat162*)(Lsec + (size_t)(m0 + 8) * 1024 + col) = l1;
            } else {
                *(float2*)(C0 + (size_t)m0 * cstride + col)       = v0;
                *(float2*)(C0 + (size_t)(m0 + 8) * cstride + col) = v1;
            }
        }
    }
}

// ---------------------------------------------------------------------------
// Flash attention on HMMA. CTA: 128 q-rows, 8 warps (16 rows each), KB=64.
// K/V tiles shared by all 8 warps (halved L2 traffic vs 64-row CTA).
// 2-stage cp.async ring. Dynamic smem: 2 x (4 tiles 64x72 bf16 + mask) = 74240 B.
// ---------------------------------------------------------------------------
__global__ __launch_bounds__(256, 2)
void attn_mma(const __nv_bfloat16* __restrict__ Qh, const __nv_bfloat16* __restrict__ Ql,
              const __nv_bfloat16* __restrict__ Kh, const __nv_bfloat16* __restrict__ Kl,
              const __nv_bfloat16* __restrict__ Vh, const __nv_bfloat16* __restrict__ Vl,
              const float* __restrict__ mask, float* __restrict__ Ctx,
              __nv_bfloat16* __restrict__ Chi, __nv_bfloat16* __restrict__ Clo)
{
    constexpr int STR = 72;
    constexpr int TILE = 64 * STR * 2;          // 9216 B (one 64x64 K/V tile)
    constexpr int QTILE = 128 * STR * 2;        // 18432 B (128x64 Q tile)
    constexpr int STAGE = 4 * TILE + 256;       // + mask, 37120 B
    extern __shared__ char dsm[];
    const uint32_t sb = smem_u32(dsm);

    const int b = blockIdx.z, h = blockIdx.y, qt = blockIdx.x;
    const int t = threadIdx.x, wid = t >> 5, lane = t & 31;
    const float scale = 0.125f;
    const int nkt = SS / 64;

    // ---- stage Q tile (128x64 hi/lo) into smem start and load fragments
    {
        const size_t qbase = (size_t)(b * SS + qt * 128) * HH + h * DHEAD;
        #pragma unroll
        for (int i = 0; i < 4; i++) {
            const int id = t + i * 256;
            const int r = id >> 3, c = (id & 7) * 8;
            *(uint4*)(dsm + (r * STR + c) * 2)         = *(const uint4*)(Qh + qbase + (size_t)r * HH + c);
            *(uint4*)(dsm + QTILE + (r * STR + c) * 2) = *(const uint4*)(Ql + qbase + (size_t)r * HH + c);
        }
    }
    __syncthreads();
    uint32_t qhf[4][4], qlf[4][4];
    {
        const int row = wid * 16 + (lane & 15);
        #pragma unroll
        for (int ks = 0; ks < 4; ks++) {
            const int kc = ks * 16 + ((lane >> 4) * 8);
            ldm_x4(qhf[ks], sb + (uint32_t)(row * STR + kc) * 2);
            ldm_x4(qlf[ks], sb + QTILE + (uint32_t)(row * STR + kc) * 2);
        }
    }
    __syncthreads();

    // ---- cp.async issue of K/V/mask for tile kt into stage kt&1
    auto issue = [&](int kt) {
        const int s = kt & 1;
        const uint32_t st = sb + s * STAGE;
        const size_t kbase = (size_t)(b * SS + kt * 64) * HH + h * DHEAD;
        const __nv_bfloat16* tp0 = Kh; const __nv_bfloat16* tp1 = Kl;
        const __nv_bfloat16* tp2 = Vh; const __nv_bfloat16* tp3 = Vl;
        #pragma unroll
        for (int i = 0; i < 8; i++) {
            const int id = t + i * 256;
            const int tile = id >> 9;
            const int r = (id >> 3) & 63, c = (id & 7) * 8;
            const __nv_bfloat16* tp = (tile == 0) ? tp0 : ((tile == 1) ? tp1 : ((tile == 2) ? tp2 : tp3));
            CP_ASYNC16(st + tile * TILE + (uint32_t)(r * STR + c) * 2,
                       tp + kbase + (size_t)r * HH + c);
        }
        if (t < 16) CP_ASYNC16(st + 4 * TILE + t * 16, mask + b * SS + kt * 64 + t * 4);
        CP_COMMIT();
    };

    // ---- flash state
    float o[8][4];
    #pragma unroll
    for (int nt = 0; nt < 8; nt++)
        #pragma unroll
        for (int r = 0; r < 4; r++) o[nt][r] = 0.f;
    float m0 = -INFINITY, m1 = -INFINITY;
    float l0 = 0.f, l1 = 0.f;

    issue(0);
    for (int kt = 0; kt < nkt; kt++) {
        if (kt + 1 < nkt) issue(kt + 1);
        if (kt + 1 < nkt) { CP_WAIT1(); } else { CP_WAIT0(); }
        __syncthreads();

        const int s = kt & 1;
        const uint32_t sKh = sb + s * STAGE;
        const uint32_t sKl = sKh + TILE;
        const uint32_t sVh = sKh + 2 * TILE;
        const uint32_t sVl = sKh + 3 * TILE;
        const float* mskp = (const float*)(dsm + s * STAGE + 4 * TILE);

        // ---- S = Qh@Kh^T + Qh@Kl^T + Ql@Kh^T  (16 x 64 per warp)
        float sacc[8][4];
        #pragma unroll
        for (int nt = 0; nt < 8; nt++)
            #pragma unroll
            for (int r = 0; r < 4; r++) sacc[nt][r] = 0.f;

        #pragma unroll
        for (int ks = 0; ks < 4; ks++) {
            #pragma unroll
            for (int nt2 = 0; nt2 < 4; nt2++) {
                uint32_t bh[4], bl[4];
                const int row = nt2 * 16 + ((lane >> 4) * 8) + (lane & 7);
                const int kc = ks * 16 + (((lane >> 3) & 1) * 8);
                const uint32_t off = (uint32_t)(row * STR + kc) * 2;
                ldm_x4(bh, sKh + off);
                ldm_x4(bl, sKl + off);
                mma16816(sacc[2 * nt2],     qhf[ks], &bh[0]);
                mma16816(sacc[2 * nt2],     qhf[ks], &bl[0]);
                mma16816(sacc[2 * nt2],     qlf[ks], &bh[0]);
                mma16816(sacc[2 * nt2 + 1], qhf[ks], &bh[2]);
                mma16816(sacc[2 * nt2 + 1], qhf[ks], &bl[2]);
                mma16816(sacc[2 * nt2 + 1], qlf[ks], &bh[2]);
            }
        }

        // ---- softmax (rows r=lane/4 and r+8; cols per nt: nt*8+(lane&3)*2,+1)
        float nm0 = m0, nm1 = m1;
        #pragma unroll
        for (int nt = 0; nt < 8; nt++) {
            const int c0 = nt * 8 + (lane & 3) * 2;
            const float mk0 = mskp[c0], mk1 = mskp[c0 + 1];
            sacc[nt][0] = sacc[nt][0] * scale + mk0;
            sacc[nt][1] = sacc[nt][1] * scale + mk1;
            sacc[nt][2] = sacc[nt][2] * scale + mk0;
            sacc[nt][3] = sacc[nt][3] * scale + mk1;
            nm0 = fmaxf(nm0, fmaxf(sacc[nt][0], sacc[nt][1]));
            nm1 = fmaxf(nm1, fmaxf(sacc[nt][2], sacc[nt][3]));
        }
        nm0 = fmaxf(nm0, __shfl_xor_sync(0xFFFFFFFFu, nm0, 1));
        nm0 = fmaxf(nm0, __shfl_xor_sync(0xFFFFFFFFu, nm0, 2));
        nm1 = fmaxf(nm1, __shfl_xor_sync(0xFFFFFFFFu, nm1, 1));
        nm1 = fmaxf(nm1, __shfl_xor_sync(0xFFFFFFFFu, nm1, 2));

        const float cr0 = __expf(m0 - nm0);
        const float cr1 = __expf(m1 - nm1);
        l0 *= cr0; l1 *= cr1;
        #pragma unroll
        for (int nt = 0; nt < 8; nt++) {
            o[nt][0] *= cr0; o[nt][1] *= cr0;
            o[nt][2] *= cr1; o[nt][3] *= cr1;
        }
        #pragma unroll
        for (int nt = 0; nt < 8; nt++) {
            sacc[nt][0] = __expf(sacc[nt][0] - nm0);
            sacc[nt][1] = __expf(sacc[nt][1] - nm0);
            sacc[nt][2] = __expf(sacc[nt][2] - nm1);
            sacc[nt][3] = __expf(sacc[nt][3] - nm1);
            l0 += sacc[nt][0] + sacc[nt][1];
            l1 += sacc[nt][2] + sacc[nt][3];
        }
        m0 = nm0; m1 = nm1;

        // ---- PV: per k-step ks, P A-frag from S n-tiles (2ks, 2ks+1)
        #pragma unroll
        for (int ks = 0; ks < 4; ks++) {
            uint32_t ph[4], pl[4];
            {
                const float* sa = sacc[2 * ks];
                const float* sbp = sacc[2 * ks + 1];
                __nv_bfloat162 hh, ll;
                float2 f;
                f.x = sa[0]; f.y = sa[1];
                hh = __float22bfloat162_rn(f);
                ll.x = __float2bfloat16_rn(f.x - __bfloat162float(hh.x));
                ll.y = __float2bfloat16_rn(f.y - __bfloat162float(hh.y));
                ph[0] = *(uint32_t*)&hh; pl[0] = *(uint32_t*)&ll;
                f.x = sa[2]; f.y = sa[3];
                hh = __float22bfloat162_rn(f);
                ll.x = __float2bfloat16_rn(f.x - __bfloat162float(hh.x));
                ll.y = __float2bfloat16_rn(f.y - __bfloat162float(hh.y));
                ph[1] = *(uint32_t*)&hh; pl[1] = *(uint32_t*)&ll;
                f.x = sbp[0]; f.y = sbp[1];
                hh = __float22bfloat162_rn(f);
                ll.x = __float2bfloat16_rn(f.x - __bfloat162float(hh.x));
                ll.y = __float2bfloat16_rn(f.y - __bfloat162float(hh.y));
                ph[2] = *(uint32_t*)&hh; pl[2] = *(uint32_t*)&ll;
                f.x = sbp[2]; f.y = sbp[3];
                hh = __float22bfloat162_rn(f);
                ll.x = __float2bfloat16_rn(f.x - __bfloat162float(hh.x));
                ll.y = __float2bfloat16_rn(f.y - __bfloat162float(hh.y));
                ph[3] = *(uint32_t*)&hh; pl[3] = *(uint32_t*)&ll;
            }
            #pragma unroll
            for (int nt2 = 0; nt2 < 4; nt2++) {
                uint32_t vh[4], vl[4];
                const int row = ks * 16 + (((lane >> 3) & 1) * 8) + (lane & 7);
                const int col = nt2 * 16 + ((lane >> 4) * 8);
                const uint32_t off = (uint32_t)(row * STR + col) * 2;
                ldm_x4t(vh, sVh + off);
                ldm_x4t(vl, sVl + off);
                mma16816(o[2 * nt2],     ph, &vh[0]);
                mma16816(o[2 * nt2],     ph, &vl[0]);
                mma16816(o[2 * nt2],     pl, &vh[0]);
                mma16816(o[2 * nt2 + 1], ph, &vh[2]);
                mma16816(o[2 * nt2 + 1], ph, &vl[2]);
                mma16816(o[2 * nt2 + 1], pl, &vh[2]);
            }
        }
        __syncthreads();
    }

    // ---- final reduce + write
    l0 += __shfl_xor_sync(0xFFFFFFFFu, l0, 1);
    l0 += __shfl_xor_sync(0xFFFFFFFFu, l0, 2);
    l1 += __shfl_xor_sync(0xFFFFFFFFu, l1, 1);
    l1 += __shfl_xor_sync(0xFFFFFFFFu, l1, 2);
    const float inv0 = 1.0f / l0;
    const float inv1 = 1.0f / l1;

    const int grow0 = b * SS + qt * 128 + wid * 16 + (lane >> 2);
    const int grow1 = grow0 + 8;
    #pragma unroll
    for (int nt = 0; nt < 8; nt++) {
        const int col = h * DHEAD + nt * 8 + (lane & 3) * 2;
        float2 v0 = { o[nt][0] * inv0, o[nt][1] * inv0 };
        float2 v1 = { o[nt][2] * inv1, o[nt][3] * inv1 };
        *(float2*)(Ctx + (size_t)grow0 * HH + col) = v0;
        *(float2*)(Ctx + (size_t)grow1 * HH + col) = v1;
        __nv_bfloat162 h0 = __float22bfloat162_rn(v0);
        __nv_bfloat162 l0b;
        l0b.x = __float2bfloat16_rn(v0.x - __bfloat162float(h0.x));
        l0b.y = __float2bfloat16_rn(v0.y - __bfloat162float(h0.y));
        __nv_bfloat162 h1 = __float22bfloat162_rn(v1);
        __nv_bfloat162 l1b;
        l1b.x = __float2bfloat16_rn(v1.x - __bfloat162float(h1.x));
        l1b.y = __float2bfloat16_rn(v1.y - __bfloat162float(h1.y));
        *(__nv_bfloat162*)(Chi + (size_t)grow0 * HH + col) = h0;
        *(__nv_bfloat162*)(Clo + (size_t)grow0 * HH + col) = l0b;
        *(__nv_bfloat162*)(Chi + (size_t)grow1 * HH + col) = h1;
        *(__nv_bfloat162*)(Clo + (size_t)grow1 * HH + col) = l1b;
    }
}

// ---------------------------------------------------------------------------
// Launch
// ---------------------------------------------------------------------------
extern "C" void kernel_launch(void* const* d_in, const int* in_sizes, int n_in,
                              void* d_out, int out_size)
{
    const float* input = (const float*)d_in[0];
    const float* mask  = (const float*)d_in[1];
    const float* nw    = (const float*)d_in[2];
    const float* nb    = (const float*)d_in[3];
    const float* qkvw  = (const float*)d_in[4];
    const float* qkvb  = (const float*)d_in[5];
    const float* ow    = (const float*)d_in[6];

    float* out     = (float*)d_out;
    float* key_out = out + (size_t)TENSOR_ELEMS;
    float* val_out = out + (size_t)2 * TENSOR_ELEMS;
    float* ctx_out = out + (size_t)3 * TENSOR_ELEMS;

    __nv_bfloat16 *a_hi, *a_lo, *w_hi, *w_lo, *ow_hi, *ow_lo;
    __nv_bfloat16 *q_hi, *q_lo, *k_hi, *k_lo, *v_hi, *v_lo, *c_hi, *c_lo;
    cudaGetSymbolAddress((void**)&a_hi, g_a_hi);
    cudaGetSymbolAddress((void**)&a_lo, g_a_lo);
    cudaGetSymbolAddress((void**)&w_hi, g_w_hi);
    cudaGetSymbolAddress((void**)&w_lo, g_w_lo);
    cudaGetSymbolAddress((void**)&ow_hi, g_ow_hi);
    cudaGetSymbolAddress((void**)&ow_lo, g_ow_lo);
    cudaGetSymbolAddress((void**)&q_hi, g_q_hi);
    cudaGetSymbolAddress((void**)&q_lo, g_q_lo);
    cudaGetSymbolAddress((void**)&k_hi, g_k_hi);
    cudaGetSymbolAddress((void**)&k_lo, g_k_lo);
    cudaGetSymbolAddress((void**)&v_hi, g_v_hi);
    cudaGetSymbolAddress((void**)&v_lo, g_v_lo);
    cudaGetSymbolAddress((void**)&c_hi, g_c_hi);
    cudaGetSymbolAddress((void**)&c_lo, g_c_lo);

    const int GEMM_DYN = 2 * 4 * 128 * 40 * 2;         // 81920
    const int ATTN_DYN = 2 * (4 * 64 * 72 * 2 + 256);  // 74240
    cudaFuncSetAttribute(gemm_mma<true>,  cudaFuncAttributeMaxDynamicSharedMemorySize, GEMM_DYN);
    cudaFuncSetAttribute(gemm_mma<false>, cudaFuncAttributeMaxDynamicSharedMemorySize, GEMM_DYN);
    cudaFuncSetAttribute(attn_mma, cudaFuncAttributeMaxDynamicSharedMemorySize, ATTN_DYN);

    // 1) LayerNorm -> bf16 split
    ln_kernel<<<MROWS, 256>>>(input, nw, nb, a_hi, a_lo);

    // 2) Weight splits
    split_kernel<<<(3 * HH * HH / 4 + 255) / 256, 256>>>(qkvw, w_hi, w_lo, 3 * HH * HH / 4);
    split_kernel<<<(HH * HH / 4 + 255) / 256, 256>>>(ow, ow_hi, ow_lo, HH * HH / 4);

    // 3) QKV GEMM: fp32 K/V outputs + bf16 hi/lo Q/K/V scratch
    {
        dim3 grid(3072 / 128, MROWS / 128);
        gemm_mma<true><<<grid, 256, GEMM_DYN>>>(a_hi, a_lo, w_hi, w_lo, qkvb,
                                                key_out, val_out, nullptr,
                                                q_hi, q_lo, k_hi, k_lo, v_hi, v_lo,
                                                HH, 3 * HH);
    }

    // 4) Flash attention (HMMA) -> ctx fp32 + ctx bf16 hi/lo
    {
        dim3 grid(SS / 128, NHEADS, BB);
        attn_mma<<<grid, 256, ATTN_DYN>>>(q_hi, q_lo, k_hi, k_lo, v_hi, v_lo,
                                          mask, ctx_out, c_hi, c_lo);
    }

    // 5) Output projection
    {
        dim3 grid(HH / 128, MROWS / 128);
        gemm_mma<false><<<grid, 256, GEMM_DYN>>>(c_hi, c_lo, ow_hi, ow_lo, nullptr,
                                                 nullptr, nullptr, out,
                                                 nullptr, nullptr, nullptr, nullptr, nullptr, nullptr,
                                                 HH, HH);
    }
}